// round 1
// baseline (speedup 1.0000x reference)
#include <cuda_runtime.h>
#include <math.h>

#define B_SZ 256
#define S_SZ 512
#define V_SZ 50000
#define E_SZ 300
#define H_SZ 1024

// Scratch: vocab projection table (205 MB), double-buffered hidden state, MLP hidden.
__device__ float g_table[(size_t)V_SZ * H_SZ];
__device__ float g_h[2 * B_SZ * H_SZ];
__device__ float g_hid[B_SZ * 2 * H_SZ];

// ---------------------------------------------------------------------------
// Generic NT GEMM: C[m,n] = sum_k A[m,k] * B[n,k]  (both row-major, K-major)
// MODE 0: plain store    (table precompute)
// MODE 1: tanh(acc + table[x[m,t]][n] + bias[n])   (RNN step)
// MODE 2: relu(acc + bias[n])                       (MLP layer 1)
// GUARD: bounds-check M and K (needed for V=50000, K=300 table GEMM)
// ---------------------------------------------------------------------------
template<int BM, int BN, int BK, int TM, int TN, int MODE, bool GUARD>
__global__ void __launch_bounds__(256) gemm_nt(
    const float* __restrict__ A, int lda,
    const float* __restrict__ B, int ldb,
    float* __restrict__ C, int ldc,
    int M, int N, int K,
    const float* __restrict__ bias,
    const float* __restrict__ table,
    const int* __restrict__ x, int t)
{
    constexpr int BNP = BN + 1;                 // pad: conflict-free scalar STS/LDS for B
    __shared__ float As[BM * BK];               // row-major [m][k]
    __shared__ float Bs[BK * BNP];              // k-major  [k][n]

    const int tid = threadIdx.x;
    const int tx = tid % (BN / TN);
    const int ty = tid / (BN / TN);
    const int m0 = blockIdx.y * BM;
    const int n0 = blockIdx.x * BN;

    constexpr int A_LD = (BM * BK / 4) / 256;   // float4 loads per thread
    constexpr int B_LD = (BN * BK / 4) / 256;
    static_assert(A_LD >= 1 && B_LD >= 1, "tile too small");

    float4 aReg[A_LD];
    float4 bReg[B_LD];

    const int KT = (K + BK - 1) / BK;

    auto loadA = [&](int kt) {
#pragma unroll
        for (int i = 0; i < A_LD; i++) {
            int idx = tid + i * 256;
            int r   = idx / (BK / 4);
            int c4  = idx % (BK / 4);
            int gm  = m0 + r;
            int gk  = kt * BK + c4 * 4;
            if (!GUARD) {
                aReg[i] = *reinterpret_cast<const float4*>(&A[(size_t)gm * lda + gk]);
            } else {
                float4 v = make_float4(0.f, 0.f, 0.f, 0.f);
                if (gm < M) {
                    const float* p = &A[(size_t)gm * lda + gk];
                    if (gk + 0 < K) v.x = p[0];
                    if (gk + 1 < K) v.y = p[1];
                    if (gk + 2 < K) v.z = p[2];
                    if (gk + 3 < K) v.w = p[3];
                }
                aReg[i] = v;
            }
        }
    };
    auto loadB = [&](int kt) {
#pragma unroll
        for (int i = 0; i < B_LD; i++) {
            int idx = tid + i * 256;
            int r   = idx / (BK / 4);           // n within tile (always < N)
            int c4  = idx % (BK / 4);
            int gn  = n0 + r;
            int gk  = kt * BK + c4 * 4;
            if (!GUARD) {
                bReg[i] = *reinterpret_cast<const float4*>(&B[(size_t)gn * ldb + gk]);
            } else {
                float4 v = make_float4(0.f, 0.f, 0.f, 0.f);
                const float* p = &B[(size_t)gn * ldb + gk];
                if (gk + 0 < K) v.x = p[0];
                if (gk + 1 < K) v.y = p[1];
                if (gk + 2 < K) v.z = p[2];
                if (gk + 3 < K) v.w = p[3];
                bReg[i] = v;
            }
        }
    };
    auto storeA = [&]() {
#pragma unroll
        for (int i = 0; i < A_LD; i++) {
            int idx = tid + i * 256;
            int r   = idx / (BK / 4);
            int c4  = idx % (BK / 4);
            *reinterpret_cast<float4*>(&As[r * BK + c4 * 4]) = aReg[i];
        }
    };
    auto storeB = [&]() {
#pragma unroll
        for (int i = 0; i < B_LD; i++) {
            int idx = tid + i * 256;
            int r   = idx / (BK / 4);
            int c4  = idx % (BK / 4);
            int kb  = c4 * 4;
            float4 v = bReg[i];
            Bs[(kb + 0) * BNP + r] = v.x;       // transpose to k-major in SMEM
            Bs[(kb + 1) * BNP + r] = v.y;
            Bs[(kb + 2) * BNP + r] = v.z;
            Bs[(kb + 3) * BNP + r] = v.w;
        }
    };

    float acc[TM][TN];
#pragma unroll
    for (int i = 0; i < TM; i++)
#pragma unroll
        for (int j = 0; j < TN; j++) acc[i][j] = 0.f;

    loadA(0); loadB(0);
    storeA(); storeB();
    __syncthreads();

    for (int kt = 0; kt < KT; kt++) {
        if (kt + 1 < KT) { loadA(kt + 1); loadB(kt + 1); }   // prefetch into regs
#pragma unroll
        for (int kk = 0; kk < BK; kk++) {
            float a[TM], b[TN];
#pragma unroll
            for (int i = 0; i < TM; i++) a[i] = As[(ty * TM + i) * BK + kk];
#pragma unroll
            for (int j = 0; j < TN; j++) b[j] = Bs[kk * BNP + tx * TN + j];
#pragma unroll
            for (int i = 0; i < TM; i++)
#pragma unroll
                for (int j = 0; j < TN; j++)
                    acc[i][j] = fmaf(a[i], b[j], acc[i][j]);
        }
        __syncthreads();
        if (kt + 1 < KT) { storeA(); storeB(); }
        __syncthreads();
    }

    // epilogue
#pragma unroll
    for (int i = 0; i < TM; i++) {
        int m = m0 + ty * TM + i;
        if (GUARD && m >= M) continue;
        const float* trow = nullptr;
        if (MODE == 1) {
            int tok = x[(size_t)m * S_SZ + t];
            trow = &table[(size_t)tok * H_SZ];
        }
#pragma unroll
        for (int j = 0; j < TN; j++) {
            int n = n0 + tx * TN + j;
            float v = acc[i][j];
            if (MODE == 1)      v = tanhf(v + trow[n] + bias[n]);
            else if (MODE == 2) v = fmaxf(v + bias[n], 0.f);
            C[(size_t)m * ldc + n] = v;
        }
    }
}

__global__ void init_zero_kernel(float* p) {
    p[blockIdx.x * 256 + threadIdx.x] = 0.f;
}

// out[b] = b2 + sum_i hid[b,i] * W2[i]
__global__ void head2_kernel(const float* __restrict__ hid,
                             const float* __restrict__ W2,
                             const float* __restrict__ b2,
                             float* __restrict__ out)
{
    __shared__ float red[256];
    int b = blockIdx.x;
    float s = 0.f;
    for (int i = threadIdx.x; i < 2 * H_SZ; i += 256)
        s += hid[(size_t)b * 2 * H_SZ + i] * W2[i];
    red[threadIdx.x] = s;
    __syncthreads();
    for (int off = 128; off > 0; off >>= 1) {
        if (threadIdx.x < off) red[threadIdx.x] += red[threadIdx.x + off];
        __syncthreads();
    }
    if (threadIdx.x == 0) out[b] = red[0] + b2[0];
}

extern "C" void kernel_launch(void* const* d_in, const int* in_sizes, int n_in,
                              void* d_out, int out_size)
{
    const int*   x       = (const int*)  d_in[0];
    const float* embed_W = (const float*)d_in[1];
    const float* W_ih    = (const float*)d_in[2];
    const float* b_ih    = (const float*)d_in[3];
    const float* W1      = (const float*)d_in[4];
    const float* b1      = (const float*)d_in[5];
    const float* W2      = (const float*)d_in[6];
    const float* b2      = (const float*)d_in[7];
    float*       out     = (float*)d_out;

    float *table, *h, *hid;
    cudaGetSymbolAddress((void**)&table, g_table);
    cudaGetSymbolAddress((void**)&h,     g_h);
    cudaGetSymbolAddress((void**)&hid,   g_hid);

    // h0 = 0
    init_zero_kernel<<<(B_SZ * H_SZ) / 256, 256>>>(h);

    // T[v,j] = embed_W[v,:] . W_e[j,:]   (W_e = W_ih[:, :E], row stride E+H)
    gemm_nt<64, 64, 32, 4, 4, 0, true>
        <<<dim3(H_SZ / 64, (V_SZ + 63) / 64), 256>>>(
            embed_W, E_SZ,
            W_ih, E_SZ + H_SZ,
            table, H_SZ,
            V_SZ, H_SZ, E_SZ,
            nullptr, nullptr, nullptr, 0);

    // 512 recurrence steps: h_new = tanh(T[x[:,t]] + h @ W_h^T + b_ih)
    for (int t = 0; t < S_SZ; t++) {
        const float* hc = h + (t & 1) * B_SZ * H_SZ;
        float*       hn = h + ((t + 1) & 1) * B_SZ * H_SZ;
        gemm_nt<32, 64, 32, 2, 4, 1, false>
            <<<dim3(H_SZ / 64, B_SZ / 32), 256>>>(
                hc, H_SZ,
                W_ih + E_SZ, E_SZ + H_SZ,   // W_h = W_ih[:, E:]
                hn, H_SZ,
                B_SZ, H_SZ, H_SZ,
                b_ih, table, x, t);
    }

    // hid = relu(h_last @ W1^T + b1); h_last is buffer 0 (512 steps, even)
    gemm_nt<64, 64, 32, 4, 4, 2, false>
        <<<dim3(2 * H_SZ / 64, B_SZ / 64), 256>>>(
            h, H_SZ,
            W1, H_SZ,
            hid, 2 * H_SZ,
            B_SZ, 2 * H_SZ, H_SZ,
            b1, nullptr, nullptr, 0);

    // out = hid @ W2^T + b2
    head2_kernel<<<B_SZ, 256>>>(hid, W2, b2, out);
}

// round 3
// speedup vs baseline: 2.7261x; 2.7261x over previous
#include <cuda_runtime.h>
#include <cuda_bf16.h>
#include <math.h>
#include <stdint.h>

#define B_SZ 256
#define S_SZ 512
#define V_SZ 50000
#define E_SZ 300
#define H_SZ 1024

// ---------------- scratch ----------------
__device__ __align__(128) __nv_bfloat16 g_h_hi[2][B_SZ * H_SZ];
__device__ __align__(128) __nv_bfloat16 g_h_lo[2][B_SZ * H_SZ];
__device__ __align__(128) __nv_bfloat16 g_w_hi[H_SZ * H_SZ];
__device__ __align__(128) __nv_bfloat16 g_w_lo[H_SZ * H_SZ];
__device__ float g_table[(size_t)V_SZ * H_SZ];
__device__ float g_hlast[B_SZ * H_SZ];
__device__ float g_hid[B_SZ * 2 * H_SZ];

// ---------------- PTX helpers (sm_80+ ISA only) ----------------
__device__ __forceinline__ uint32_t smem_u32(const void* p) {
    return (uint32_t)__cvta_generic_to_shared(p);
}
__device__ __forceinline__ void cp16(uint32_t dst, const void* src) {
    asm volatile("cp.async.cg.shared.global [%0], [%1], 16;" :: "r"(dst), "l"(src));
}
#define CP_COMMIT() asm volatile("cp.async.commit_group;" ::: "memory")
#define CP_WAIT2()  asm volatile("cp.async.wait_group 2;" ::: "memory")

__device__ __forceinline__ void ldmx4(uint32_t* r, uint32_t addr) {
    asm volatile("ldmatrix.sync.aligned.m8n8.x4.shared.b16 {%0,%1,%2,%3}, [%4];"
        : "=r"(r[0]), "=r"(r[1]), "=r"(r[2]), "=r"(r[3]) : "r"(addr));
}
__device__ __forceinline__ void mma16816(float* d, const uint32_t* a,
                                         const uint32_t b0, const uint32_t b1) {
    asm volatile("mma.sync.aligned.m16n8k16.row.col.f32.bf16.bf16.f32 "
        "{%0,%1,%2,%3}, {%4,%5,%6,%7}, {%8,%9}, {%0,%1,%2,%3};"
        : "+f"(d[0]), "+f"(d[1]), "+f"(d[2]), "+f"(d[3])
        : "r"(a[0]), "r"(a[1]), "r"(a[2]), "r"(a[3]), "r"(b0), "r"(b1));
}

// ---------------- step kernel (bf16-split mma.sync) ----------------
// C[m,n] = sum_k (hhi+hlo)[m,k]*(whi+wlo)[n,k], dropping lo*lo.
// CTA tile 32(M) x 64(N), 4 warps of 16x32.  K chunk = 32, 3-stage cp.async.
#define STG_A   2048                 // 32 rows * 64B
#define STG_W   4096                 // 64 rows * 64B
#define STG_SZ  (2*STG_A + 2*STG_W)  // 12288
#define NSTAGE  3
#define NCHUNK  (H_SZ / 32)          // 32

__global__ void __launch_bounds__(128, 1) step_kernel(
    const __nv_bfloat16* __restrict__ hhi,
    const __nv_bfloat16* __restrict__ hlo,
    const __nv_bfloat16* __restrict__ whi,
    const __nv_bfloat16* __restrict__ wlo,
    const float* __restrict__ table,
    const float* __restrict__ bias,
    const int* __restrict__ x, int t,
    __nv_bfloat16* __restrict__ out_hi,
    __nv_bfloat16* __restrict__ out_lo)
{
    __shared__ __align__(128) char smem[NSTAGE * STG_SZ];

    const int tid  = threadIdx.x;
    const int lane = tid & 31;
    const int wid  = tid >> 5;
    const int wm   = wid >> 1;        // 0..1 -> m offset 16*wm
    const int wn   = wid & 1;         // 0..1 -> n offset 32*wn
    const int n0   = blockIdx.x * 64;
    const int m0   = blockIdx.y * 32;
    const uint32_t sb = smem_u32(smem);

    // ---- async stage loader: 768 x 16B units, 6 per thread ----
    auto issue_stage = [&](uint32_t sbase, int kblk) {
#pragma unroll
        for (int i = 0; i < 6; i++) {
            int u = tid + i * 128;
            if (u < 256) {                               // A tiles (hi, lo)
                int term = u >> 7;
                int v = u & 127;
                int r = v >> 2, c = v & 3;
                const __nv_bfloat16* src = (term ? hlo : hhi)
                    + (size_t)(m0 + r) * H_SZ + kblk * 32 + c * 8;
                uint32_t dst = sbase + term * STG_A + r * 64
                             + ((c ^ ((r >> 1) & 3)) << 4);
                cp16(dst, src);
            } else {                                     // W tiles (hi, lo)
                int v = u - 256;
                int term = v >> 8;
                v &= 255;
                int r = v >> 2, c = v & 3;
                const __nv_bfloat16* src = (term ? wlo : whi)
                    + (size_t)(n0 + r) * H_SZ + kblk * 32 + c * 8;
                uint32_t dst = sbase + 2 * STG_A + term * STG_W + r * 64
                             + ((c ^ ((r >> 1) & 3)) << 4);
                cp16(dst, src);
            }
        }
        CP_COMMIT();
    };

    // prologue: fill 3 stages
    issue_stage(sb + 0 * STG_SZ, 0);
    issue_stage(sb + 1 * STG_SZ, 1);
    issue_stage(sb + 2 * STG_SZ, 2);

    // ---- precomputed ldmatrix lane geometry ----
    // A: row = wm*16 + (lane&15), k-unit add = lane>>4
    const int rowA = wm * 16 + (lane & 15);
    const int cAadd = lane >> 4;
    const int swzA = (rowA >> 1) & 3;
    // B: row = wn*32 + hh*16 + ((lane>>4)<<3) + (lane&7), k-unit add = (lane>>3)&1
    const int rowB0 = wn * 32 + ((lane >> 4) << 3) + (lane & 7);       // hh=0
    const int rowB1 = rowB0 + 16;                                      // hh=1
    const int cBadd = (lane >> 3) & 1;
    const int swzB0 = (rowB0 >> 1) & 3;
    const int swzB1 = (rowB1 >> 1) & 3;

    float acc[4][4];
#pragma unroll
    for (int j = 0; j < 4; j++)
#pragma unroll
        for (int q = 0; q < 4; q++) acc[j][q] = 0.f;

    for (int ch = 0; ch < NCHUNK; ch++) {
        const uint32_t st = sb + (ch % NSTAGE) * STG_SZ;
        CP_WAIT2();
        __syncthreads();

#pragma unroll
        for (int kk = 0; kk < 2; kk++) {
            const int cA = ((kk * 2 + cAadd) ^ swzA) << 4;
            const int cB0 = ((kk * 2 + cBadd) ^ swzB0) << 4;
            const int cB1 = ((kk * 2 + cBadd) ^ swzB1) << 4;
            uint32_t ahi[4], alo[4], bhi[8], blo[8];
            ldmx4(ahi, st + 0 * STG_A + rowA * 64 + cA);
            ldmx4(alo, st + 1 * STG_A + rowA * 64 + cA);
            ldmx4(bhi,     st + 2 * STG_A + 0 * STG_W + rowB0 * 64 + cB0);
            ldmx4(bhi + 4, st + 2 * STG_A + 0 * STG_W + rowB1 * 64 + cB1);
            ldmx4(blo,     st + 2 * STG_A + 1 * STG_W + rowB0 * 64 + cB0);
            ldmx4(blo + 4, st + 2 * STG_A + 1 * STG_W + rowB1 * 64 + cB1);
#pragma unroll
            for (int j = 0; j < 4; j++) {
                const uint32_t* bh = &bhi[(j >> 1) * 4 + (j & 1) * 2];
                const uint32_t* bl = &blo[(j >> 1) * 4 + (j & 1) * 2];
                mma16816(acc[j], ahi, bh[0], bh[1]);
                mma16816(acc[j], ahi, bl[0], bl[1]);
                mma16816(acc[j], alo, bh[0], bh[1]);
            }
        }
        __syncthreads();
        if (ch + NSTAGE < NCHUNK) issue_stage(st, ch + NSTAGE);
        else CP_COMMIT();                        // keep group count constant
    }

    // ---- epilogue: + table[tok] + bias, tanh, re-split to bf16 hi/lo ----
    const int r0 = m0 + wm * 16 + (lane >> 2);
    const int r1 = r0 + 8;
    const int tok0 = x[(size_t)r0 * S_SZ + t];
    const int tok1 = x[(size_t)r1 * S_SZ + t];
    const float* tr0 = table + (size_t)tok0 * H_SZ;
    const float* tr1 = table + (size_t)tok1 * H_SZ;

#pragma unroll
    for (int j = 0; j < 4; j++) {
        const int n = n0 + wn * 32 + j * 8 + 2 * (lane & 3);
#pragma unroll
        for (int rr = 0; rr < 2; rr++) {
            const int m = rr ? r1 : r0;
            const float* tr = rr ? tr1 : tr0;
            float v0 = tanhf(acc[j][rr * 2 + 0] + tr[n]     + bias[n]);
            float v1 = tanhf(acc[j][rr * 2 + 1] + tr[n + 1] + bias[n + 1]);
            __nv_bfloat16 h0 = __float2bfloat16(v0);
            __nv_bfloat16 h1 = __float2bfloat16(v1);
            __nv_bfloat16 l0 = __float2bfloat16(v0 - __bfloat162float(h0));
            __nv_bfloat16 l1 = __float2bfloat16(v1 - __bfloat162float(h1));
            *reinterpret_cast<__nv_bfloat162*>(out_hi + (size_t)m * H_SZ + n) =
                __nv_bfloat162(h0, h1);
            *reinterpret_cast<__nv_bfloat162*>(out_lo + (size_t)m * H_SZ + n) =
                __nv_bfloat162(l0, l1);
        }
    }
}

// ---------------- prep / misc ----------------
__global__ void split_w_kernel(const float* __restrict__ W_ih,
                               __nv_bfloat16* __restrict__ whi,
                               __nv_bfloat16* __restrict__ wlo)
{
    int i = blockIdx.x * 256 + threadIdx.x;
    int j = i >> 10, k = i & (H_SZ - 1);
    float w = W_ih[(size_t)j * (E_SZ + H_SZ) + E_SZ + k];
    __nv_bfloat16 hi = __float2bfloat16(w);
    whi[i] = hi;
    wlo[i] = __float2bfloat16(w - __bfloat162float(hi));
}

__global__ void zero_h_kernel(__nv_bfloat16* hi, __nv_bfloat16* lo) {
    int i = blockIdx.x * 256 + threadIdx.x;
    hi[i] = __float2bfloat16(0.f);
    lo[i] = __float2bfloat16(0.f);
}

__global__ void recon_h_kernel(const __nv_bfloat16* __restrict__ hi,
                               const __nv_bfloat16* __restrict__ lo,
                               float* __restrict__ out) {
    int i = blockIdx.x * 256 + threadIdx.x;
    out[i] = __bfloat162float(hi[i]) + __bfloat162float(lo[i]);
}

// ---------------- SIMT GEMM (table precompute + MLP L1) ----------------
template<int BM, int BN, int BK, int TM, int TN, int MODE, bool GUARD>
__global__ void __launch_bounds__(256) gemm_nt(
    const float* __restrict__ A, int lda,
    const float* __restrict__ B, int ldb,
    float* __restrict__ C, int ldc,
    int M, int N, int K,
    const float* __restrict__ bias)
{
    constexpr int BNP = BN + 1;
    __shared__ float As[BM * BK];
    __shared__ float Bs[BK * BNP];
    const int tid = threadIdx.x;
    const int tx = tid % (BN / TN);
    const int ty = tid / (BN / TN);
    const int m0 = blockIdx.y * BM;
    const int n0 = blockIdx.x * BN;
    constexpr int A_LD = (BM * BK / 4) / 256;
    constexpr int B_LD = (BN * BK / 4) / 256;
    float4 aReg[A_LD], bReg[B_LD];
    const int KT = (K + BK - 1) / BK;

    auto loadA = [&](int kt) {
#pragma unroll
        for (int i = 0; i < A_LD; i++) {
            int idx = tid + i * 256;
            int r = idx / (BK / 4), c4 = idx % (BK / 4);
            int gm = m0 + r, gk = kt * BK + c4 * 4;
            if (!GUARD) aReg[i] = *reinterpret_cast<const float4*>(&A[(size_t)gm * lda + gk]);
            else {
                float4 v = make_float4(0.f, 0.f, 0.f, 0.f);
                if (gm < M) {
                    const float* p = &A[(size_t)gm * lda + gk];
                    if (gk + 0 < K) v.x = p[0];
                    if (gk + 1 < K) v.y = p[1];
                    if (gk + 2 < K) v.z = p[2];
                    if (gk + 3 < K) v.w = p[3];
                }
                aReg[i] = v;
            }
        }
    };
    auto loadB = [&](int kt) {
#pragma unroll
        for (int i = 0; i < B_LD; i++) {
            int idx = tid + i * 256;
            int r = idx / (BK / 4), c4 = idx % (BK / 4);
            int gn = n0 + r, gk = kt * BK + c4 * 4;
            if (!GUARD) bReg[i] = *reinterpret_cast<const float4*>(&B[(size_t)gn * ldb + gk]);
            else {
                float4 v = make_float4(0.f, 0.f, 0.f, 0.f);
                const float* p = &B[(size_t)gn * ldb + gk];
                if (gk + 0 < K) v.x = p[0];
                if (gk + 1 < K) v.y = p[1];
                if (gk + 2 < K) v.z = p[2];
                if (gk + 3 < K) v.w = p[3];
                bReg[i] = v;
            }
        }
    };
    auto storeA = [&]() {
#pragma unroll
        for (int i = 0; i < A_LD; i++) {
            int idx = tid + i * 256;
            int r = idx / (BK / 4), c4 = idx % (BK / 4);
            *reinterpret_cast<float4*>(&As[r * BK + c4 * 4]) = aReg[i];
        }
    };
    auto storeB = [&]() {
#pragma unroll
        for (int i = 0; i < B_LD; i++) {
            int idx = tid + i * 256;
            int r = idx / (BK / 4), c4 = idx % (BK / 4);
            int kb = c4 * 4;
            float4 v = bReg[i];
            Bs[(kb + 0) * BNP + r] = v.x;
            Bs[(kb + 1) * BNP + r] = v.y;
            Bs[(kb + 2) * BNP + r] = v.z;
            Bs[(kb + 3) * BNP + r] = v.w;
        }
    };

    float acc[TM][TN];
#pragma unroll
    for (int i = 0; i < TM; i++)
#pragma unroll
        for (int j = 0; j < TN; j++) acc[i][j] = 0.f;

    loadA(0); loadB(0); storeA(); storeB();
    __syncthreads();
    for (int kt = 0; kt < KT; kt++) {
        if (kt + 1 < KT) { loadA(kt + 1); loadB(kt + 1); }
#pragma unroll
        for (int kk = 0; kk < BK; kk++) {
            float a[TM], b[TN];
#pragma unroll
            for (int i = 0; i < TM; i++) a[i] = As[(ty * TM + i) * BK + kk];
#pragma unroll
            for (int j = 0; j < TN; j++) b[j] = Bs[kk * BNP + tx * TN + j];
#pragma unroll
            for (int i = 0; i < TM; i++)
#pragma unroll
                for (int j = 0; j < TN; j++)
                    acc[i][j] = fmaf(a[i], b[j], acc[i][j]);
        }
        __syncthreads();
        if (kt + 1 < KT) { storeA(); storeB(); }
        __syncthreads();
    }
#pragma unroll
    for (int i = 0; i < TM; i++) {
        int m = m0 + ty * TM + i;
        if (GUARD && m >= M) continue;
#pragma unroll
        for (int j = 0; j < TN; j++) {
            int n = n0 + tx * TN + j;
            float v = acc[i][j];
            if (MODE == 2) v = fmaxf(v + bias[n], 0.f);
            C[(size_t)m * ldc + n] = v;
        }
    }
}

__global__ void head2_kernel(const float* __restrict__ hid,
                             const float* __restrict__ W2,
                             const float* __restrict__ b2,
                             float* __restrict__ out)
{
    __shared__ float red[256];
    int b = blockIdx.x;
    float s = 0.f;
    for (int i = threadIdx.x; i < 2 * H_SZ; i += 256)
        s += hid[(size_t)b * 2 * H_SZ + i] * W2[i];
    red[threadIdx.x] = s;
    __syncthreads();
    for (int off = 128; off > 0; off >>= 1) {
        if (threadIdx.x < off) red[threadIdx.x] += red[threadIdx.x + off];
        __syncthreads();
    }
    if (threadIdx.x == 0) out[b] = red[0] + b2[0];
}

// ---------------- host ----------------
extern "C" void kernel_launch(void* const* d_in, const int* in_sizes, int n_in,
                              void* d_out, int out_size)
{
    const int*   x       = (const int*)  d_in[0];
    const float* embed_W = (const float*)d_in[1];
    const float* W_ih    = (const float*)d_in[2];
    const float* b_ih    = (const float*)d_in[3];
    const float* W1      = (const float*)d_in[4];
    const float* b1      = (const float*)d_in[5];
    const float* W2      = (const float*)d_in[6];
    const float* b2      = (const float*)d_in[7];
    float*       out     = (float*)d_out;

    float *table, *hlast, *hid;
    __nv_bfloat16 *hhi0, *hhi1, *hlo0, *hlo1, *whi, *wlo;
    cudaGetSymbolAddress((void**)&table, g_table);
    cudaGetSymbolAddress((void**)&hlast, g_hlast);
    cudaGetSymbolAddress((void**)&hid,   g_hid);
    {
        __nv_bfloat16* p;
        cudaGetSymbolAddress((void**)&p, g_h_hi); hhi0 = p; hhi1 = p + B_SZ * H_SZ;
        cudaGetSymbolAddress((void**)&p, g_h_lo); hlo0 = p; hlo1 = p + B_SZ * H_SZ;
        cudaGetSymbolAddress((void**)&p, g_w_hi); whi = p;
        cudaGetSymbolAddress((void**)&p, g_w_lo); wlo = p;
    }

    // h0 = 0 (buffer 0)
    zero_h_kernel<<<(B_SZ * H_SZ) / 256, 256>>>(hhi0, hlo0);
    // split W_h into bf16 hi/lo
    split_w_kernel<<<(H_SZ * H_SZ) / 256, 256>>>(W_ih, whi, wlo);
    // vocab table: T[v,j] = embed_W[v,:] . W_e[j,:]
    gemm_nt<64, 64, 32, 4, 4, 0, true>
        <<<dim3(H_SZ / 64, (V_SZ + 63) / 64), 256>>>(
            embed_W, E_SZ, W_ih, E_SZ + H_SZ, table, H_SZ,
            V_SZ, H_SZ, E_SZ, nullptr);

    // 512 recurrence steps (tensor cores via mma.sync)
    for (int t = 0; t < S_SZ; t++) {
        int ib = t & 1;
        const __nv_bfloat16* ihi = ib ? hhi1 : hhi0;
        const __nv_bfloat16* ilo = ib ? hlo1 : hlo0;
        __nv_bfloat16* ohi = ib ? hhi0 : hhi1;
        __nv_bfloat16* olo = ib ? hlo0 : hlo1;
        step_kernel<<<dim3(H_SZ / 64, B_SZ / 32), 128>>>(
            ihi, ilo, whi, wlo, table, b_ih, x, t, ohi, olo);
    }

    // h_last lives in buffer 0 (512 even steps)
    recon_h_kernel<<<(B_SZ * H_SZ) / 256, 256>>>(hhi0, hlo0, hlast);

    gemm_nt<64, 64, 32, 4, 4, 2, false>
        <<<dim3(2 * H_SZ / 64, B_SZ / 64), 256>>>(
            hlast, H_SZ, W1, H_SZ, hid, 2 * H_SZ,
            B_SZ, 2 * H_SZ, H_SZ, b1);

    head2_kernel<<<B_SZ, 256>>>(hid, W2, b2, out);
}

// round 4
// speedup vs baseline: 2.8375x; 1.0409x over previous
#include <cuda_runtime.h>
#include <cuda_bf16.h>
#include <math.h>
#include <stdint.h>

#define B_SZ 256
#define S_SZ 512
#define V_SZ 50000
#define E_SZ 300
#define H_SZ 1024

// ---------------- scratch ----------------
__device__ __align__(128) __nv_bfloat16 g_h_hi[2][B_SZ * H_SZ];
__device__ __align__(128) __nv_bfloat16 g_h_lo[2][B_SZ * H_SZ];
__device__ __align__(128) __nv_bfloat16 g_w_hi[H_SZ * H_SZ];
__device__ __align__(128) __nv_bfloat16 g_w_lo[H_SZ * H_SZ];
__device__ float g_table[(size_t)V_SZ * H_SZ];
__device__ float g_hlast[B_SZ * H_SZ];
__device__ float g_hid[B_SZ * 2 * H_SZ];
__device__ __align__(128) float g_part[2 * 128 * 2048];   // per khalf, per tile
__device__ int g_cnt[128];

// ---------------- PTX helpers (sm_80+ ISA only) ----------------
__device__ __forceinline__ uint32_t smem_u32(const void* p) {
    return (uint32_t)__cvta_generic_to_shared(p);
}
__device__ __forceinline__ void cp16(uint32_t dst, const void* src) {
    asm volatile("cp.async.cg.shared.global [%0], [%1], 16;" :: "r"(dst), "l"(src));
}
#define CP_COMMIT() asm volatile("cp.async.commit_group;" ::: "memory")
#define CP_WAIT2()  asm volatile("cp.async.wait_group 2;" ::: "memory")

__device__ __forceinline__ void ldmx4(uint32_t* r, uint32_t addr) {
    asm volatile("ldmatrix.sync.aligned.m8n8.x4.shared.b16 {%0,%1,%2,%3}, [%4];"
        : "=r"(r[0]), "=r"(r[1]), "=r"(r[2]), "=r"(r[3]) : "r"(addr));
}
__device__ __forceinline__ void mma16816(float* d, const uint32_t* a,
                                         const uint32_t b0, const uint32_t b1) {
    asm volatile("mma.sync.aligned.m16n8k16.row.col.f32.bf16.bf16.f32 "
        "{%0,%1,%2,%3}, {%4,%5,%6,%7}, {%8,%9}, {%0,%1,%2,%3};"
        : "+f"(d[0]), "+f"(d[1]), "+f"(d[2]), "+f"(d[3])
        : "r"(a[0]), "r"(a[1]), "r"(a[2]), "r"(a[3]), "r"(b0), "r"(b1));
}

// ---------------- step kernel (bf16-split mma.sync, split-K x2) ----------------
// Tile 32(M) x 64(N); grid (2 khalf, 16 ntile, 8 mtile) = 256 CTAs, 4 warps.
// Each CTA accumulates K=512 (16 chunks of 32).  Second finisher CTA of each
// pair sums both partials (fixed slot order -> deterministic) + epilogue.
#define STG_A   2048                 // 32 rows * 64B
#define STG_W   4096                 // 64 rows * 64B
#define STG_SZ  (2*STG_A + 2*STG_W)  // 12288
#define NSTAGE  3
#define NCHUNK_HALF 16               // 512 / 32

__global__ void __launch_bounds__(128, 2) step_kernel(
    const __nv_bfloat16* __restrict__ hhi,
    const __nv_bfloat16* __restrict__ hlo,
    const __nv_bfloat16* __restrict__ whi,
    const __nv_bfloat16* __restrict__ wlo,
    const float* __restrict__ table,
    const float* __restrict__ bias,
    const int* __restrict__ x, int t,
    __nv_bfloat16* __restrict__ out_hi,
    __nv_bfloat16* __restrict__ out_lo,
    float* __restrict__ part,
    int* __restrict__ cnt)
{
    __shared__ __align__(128) char smem[NSTAGE * STG_SZ];
    __shared__ int s_ord;

    const int tid  = threadIdx.x;
    const int lane = tid & 31;
    const int wid  = tid >> 5;
    const int wm   = wid >> 1;
    const int wn   = wid & 1;
    const int khalf = blockIdx.x;
    const int n0   = blockIdx.y * 64;
    const int m0   = blockIdx.z * 32;
    const int tile = blockIdx.y + (blockIdx.z << 4);
    const int kbase = khalf * NCHUNK_HALF;
    const uint32_t sb = smem_u32(smem);

    auto issue_stage = [&](uint32_t sbase, int kblk) {
#pragma unroll
        for (int i = 0; i < 6; i++) {
            int u = tid + i * 128;
            if (u < 256) {                               // A tiles (hi, lo)
                int term = u >> 7;
                int v = u & 127;
                int r = v >> 2, c = v & 3;
                const __nv_bfloat16* src = (term ? hlo : hhi)
                    + (size_t)(m0 + r) * H_SZ + kblk * 32 + c * 8;
                uint32_t dst = sbase + term * STG_A + r * 64
                             + ((c ^ ((r >> 1) & 3)) << 4);
                cp16(dst, src);
            } else {                                     // W tiles (hi, lo)
                int v = u - 256;
                int term = v >> 8;
                v &= 255;
                int r = v >> 2, c = v & 3;
                const __nv_bfloat16* src = (term ? wlo : whi)
                    + (size_t)(n0 + r) * H_SZ + kblk * 32 + c * 8;
                uint32_t dst = sbase + 2 * STG_A + term * STG_W + r * 64
                             + ((c ^ ((r >> 1) & 3)) << 4);
                cp16(dst, src);
            }
        }
        CP_COMMIT();
    };

    issue_stage(sb + 0 * STG_SZ, kbase + 0);
    issue_stage(sb + 1 * STG_SZ, kbase + 1);
    issue_stage(sb + 2 * STG_SZ, kbase + 2);

    const int rowA = wm * 16 + (lane & 15);
    const int cAadd = lane >> 4;
    const int swzA = (rowA >> 1) & 3;
    const int rowB0 = wn * 32 + ((lane >> 4) << 3) + (lane & 7);
    const int rowB1 = rowB0 + 16;
    const int cBadd = (lane >> 3) & 1;
    const int swzB0 = (rowB0 >> 1) & 3;
    const int swzB1 = (rowB1 >> 1) & 3;

    float acc[4][4];
#pragma unroll
    for (int j = 0; j < 4; j++)
#pragma unroll
        for (int q = 0; q < 4; q++) acc[j][q] = 0.f;

    for (int ch = 0; ch < NCHUNK_HALF; ch++) {
        const uint32_t st = sb + (ch % NSTAGE) * STG_SZ;
        CP_WAIT2();
        __syncthreads();

#pragma unroll
        for (int kk = 0; kk < 2; kk++) {
            const int cA  = ((kk * 2 + cAadd) ^ swzA) << 4;
            const int cB0 = ((kk * 2 + cBadd) ^ swzB0) << 4;
            const int cB1 = ((kk * 2 + cBadd) ^ swzB1) << 4;
            uint32_t ahi[4], alo[4], bhi[8], blo[8];
            ldmx4(ahi, st + 0 * STG_A + rowA * 64 + cA);
            ldmx4(alo, st + 1 * STG_A + rowA * 64 + cA);
            ldmx4(bhi,     st + 2 * STG_A + 0 * STG_W + rowB0 * 64 + cB0);
            ldmx4(bhi + 4, st + 2 * STG_A + 0 * STG_W + rowB1 * 64 + cB1);
            ldmx4(blo,     st + 2 * STG_A + 1 * STG_W + rowB0 * 64 + cB0);
            ldmx4(blo + 4, st + 2 * STG_A + 1 * STG_W + rowB1 * 64 + cB1);
#pragma unroll
            for (int j = 0; j < 4; j++) {
                const uint32_t* bh = &bhi[(j >> 1) * 4 + (j & 1) * 2];
                const uint32_t* bl = &blo[(j >> 1) * 4 + (j & 1) * 2];
                mma16816(acc[j], ahi, bh[0], bh[1]);
                mma16816(acc[j], ahi, bl[0], bl[1]);
                mma16816(acc[j], alo, bh[0], bh[1]);
            }
        }
        __syncthreads();
        if (ch + NSTAGE < NCHUNK_HALF) issue_stage(st, kbase + ch + NSTAGE);
        else CP_COMMIT();
    }

    // ---- store my partial (both CTAs of the pair) ----
    float4* myp = reinterpret_cast<float4*>(
        part + (((size_t)khalf << 7) + tile) * 2048) + tid * 4;
#pragma unroll
    for (int j = 0; j < 4; j++)
        myp[j] = make_float4(acc[j][0], acc[j][1], acc[j][2], acc[j][3]);
    __threadfence();
    __syncthreads();
    if (tid == 0) s_ord = atomicAdd(&cnt[tile], 1);
    __syncthreads();
    if (s_ord == 0) return;                      // first arriver: done
    __threadfence();                             // acquire partner's partial

    // ---- finisher: sum both partials in fixed slot order ----
    const float4* p0 = reinterpret_cast<const float4*>(
        part + (size_t)tile * 2048) + tid * 4;
    const float4* p1 = reinterpret_cast<const float4*>(
        part + ((size_t)128 + tile) * 2048) + tid * 4;
    float s[4][4];
#pragma unroll
    for (int j = 0; j < 4; j++) {
        float4 a = p0[j], b = p1[j];
        s[j][0] = a.x + b.x; s[j][1] = a.y + b.y;
        s[j][2] = a.z + b.z; s[j][3] = a.w + b.w;
    }

    const int r0 = m0 + wm * 16 + (lane >> 2);
    const int r1 = r0 + 8;
    const int tok0 = x[(size_t)r0 * S_SZ + t];
    const int tok1 = x[(size_t)r1 * S_SZ + t];
    const float* tr0 = table + (size_t)tok0 * H_SZ;
    const float* tr1 = table + (size_t)tok1 * H_SZ;

#pragma unroll
    for (int j = 0; j < 4; j++) {
        const int n = n0 + wn * 32 + j * 8 + 2 * (lane & 3);
#pragma unroll
        for (int rr = 0; rr < 2; rr++) {
            const int m = rr ? r1 : r0;
            const float* tr = rr ? tr1 : tr0;
            float v0 = tanhf(s[j][rr * 2 + 0] + tr[n]     + bias[n]);
            float v1 = tanhf(s[j][rr * 2 + 1] + tr[n + 1] + bias[n + 1]);
            __nv_bfloat16 h0 = __float2bfloat16(v0);
            __nv_bfloat16 h1 = __float2bfloat16(v1);
            __nv_bfloat16 l0 = __float2bfloat16(v0 - __bfloat162float(h0));
            __nv_bfloat16 l1 = __float2bfloat16(v1 - __bfloat162float(h1));
            *reinterpret_cast<__nv_bfloat162*>(out_hi + (size_t)m * H_SZ + n) =
                __nv_bfloat162(h0, h1);
            *reinterpret_cast<__nv_bfloat162*>(out_lo + (size_t)m * H_SZ + n) =
                __nv_bfloat162(l0, l1);
        }
    }

    __syncthreads();
    if (tid == 0) cnt[tile] = 0;                 // reset for next step
}

// ---------------- prep / misc ----------------
__global__ void split_w_kernel(const float* __restrict__ W_ih,
                               __nv_bfloat16* __restrict__ whi,
                               __nv_bfloat16* __restrict__ wlo)
{
    int i = blockIdx.x * 256 + threadIdx.x;
    int j = i >> 10, k = i & (H_SZ - 1);
    float w = W_ih[(size_t)j * (E_SZ + H_SZ) + E_SZ + k];
    __nv_bfloat16 hi = __float2bfloat16(w);
    whi[i] = hi;
    wlo[i] = __float2bfloat16(w - __bfloat162float(hi));
}

__global__ void zero_h_kernel(__nv_bfloat16* hi, __nv_bfloat16* lo, int* cnt) {
    int i = blockIdx.x * 256 + threadIdx.x;
    hi[i] = __float2bfloat16(0.f);
    lo[i] = __float2bfloat16(0.f);
    if (i < 128) cnt[i] = 0;
}

__global__ void recon_h_kernel(const __nv_bfloat16* __restrict__ hi,
                               const __nv_bfloat16* __restrict__ lo,
                               float* __restrict__ out) {
    int i = blockIdx.x * 256 + threadIdx.x;
    out[i] = __bfloat162float(hi[i]) + __bfloat162float(lo[i]);
}

// ---------------- SIMT GEMM (table precompute + MLP L1) ----------------
template<int BM, int BN, int BK, int TM, int TN, int MODE, bool GUARD>
__global__ void __launch_bounds__(256) gemm_nt(
    const float* __restrict__ A, int lda,
    const float* __restrict__ B, int ldb,
    float* __restrict__ C, int ldc,
    int M, int N, int K,
    const float* __restrict__ bias)
{
    constexpr int BNP = BN + 1;
    __shared__ float As[BM * BK];
    __shared__ float Bs[BK * BNP];
    const int tid = threadIdx.x;
    const int tx = tid % (BN / TN);
    const int ty = tid / (BN / TN);
    const int m0 = blockIdx.y * BM;
    const int n0 = blockIdx.x * BN;
    constexpr int A_LD = (BM * BK / 4) / 256;
    constexpr int B_LD = (BN * BK / 4) / 256;
    float4 aReg[A_LD], bReg[B_LD];
    const int KT = (K + BK - 1) / BK;

    auto loadA = [&](int kt) {
#pragma unroll
        for (int i = 0; i < A_LD; i++) {
            int idx = tid + i * 256;
            int r = idx / (BK / 4), c4 = idx % (BK / 4);
            int gm = m0 + r, gk = kt * BK + c4 * 4;
            if (!GUARD) aReg[i] = *reinterpret_cast<const float4*>(&A[(size_t)gm * lda + gk]);
            else {
                float4 v = make_float4(0.f, 0.f, 0.f, 0.f);
                if (gm < M) {
                    const float* p = &A[(size_t)gm * lda + gk];
                    if (gk + 0 < K) v.x = p[0];
                    if (gk + 1 < K) v.y = p[1];
                    if (gk + 2 < K) v.z = p[2];
                    if (gk + 3 < K) v.w = p[3];
                }
                aReg[i] = v;
            }
        }
    };
    auto loadB = [&](int kt) {
#pragma unroll
        for (int i = 0; i < B_LD; i++) {
            int idx = tid + i * 256;
            int r = idx / (BK / 4), c4 = idx % (BK / 4);
            int gn = n0 + r, gk = kt * BK + c4 * 4;
            if (!GUARD) bReg[i] = *reinterpret_cast<const float4*>(&B[(size_t)gn * ldb + gk]);
            else {
                float4 v = make_float4(0.f, 0.f, 0.f, 0.f);
                const float* p = &B[(size_t)gn * ldb + gk];
                if (gk + 0 < K) v.x = p[0];
                if (gk + 1 < K) v.y = p[1];
                if (gk + 2 < K) v.z = p[2];
                if (gk + 3 < K) v.w = p[3];
                bReg[i] = v;
            }
        }
    };
    auto storeA = [&]() {
#pragma unroll
        for (int i = 0; i < A_LD; i++) {
            int idx = tid + i * 256;
            int r = idx / (BK / 4), c4 = idx % (BK / 4);
            *reinterpret_cast<float4*>(&As[r * BK + c4 * 4]) = aReg[i];
        }
    };
    auto storeB = [&]() {
#pragma unroll
        for (int i = 0; i < B_LD; i++) {
            int idx = tid + i * 256;
            int r = idx / (BK / 4), c4 = idx % (BK / 4);
            int kb = c4 * 4;
            float4 v = bReg[i];
            Bs[(kb + 0) * BNP + r] = v.x;
            Bs[(kb + 1) * BNP + r] = v.y;
            Bs[(kb + 2) * BNP + r] = v.z;
            Bs[(kb + 3) * BNP + r] = v.w;
        }
    };

    float acc[TM][TN];
#pragma unroll
    for (int i = 0; i < TM; i++)
#pragma unroll
        for (int j = 0; j < TN; j++) acc[i][j] = 0.f;

    loadA(0); loadB(0); storeA(); storeB();
    __syncthreads();
    for (int kt = 0; kt < KT; kt++) {
        if (kt + 1 < KT) { loadA(kt + 1); loadB(kt + 1); }
#pragma unroll
        for (int kk = 0; kk < BK; kk++) {
            float a[TM], b[TN];
#pragma unroll
            for (int i = 0; i < TM; i++) a[i] = As[(ty * TM + i) * BK + kk];
#pragma unroll
            for (int j = 0; j < TN; j++) b[j] = Bs[kk * BNP + tx * TN + j];
#pragma unroll
            for (int i = 0; i < TM; i++)
#pragma unroll
                for (int j = 0; j < TN; j++)
                    acc[i][j] = fmaf(a[i], b[j], acc[i][j]);
        }
        __syncthreads();
        if (kt + 1 < KT) { storeA(); storeB(); }
        __syncthreads();
    }
#pragma unroll
    for (int i = 0; i < TM; i++) {
        int m = m0 + ty * TM + i;
        if (GUARD && m >= M) continue;
#pragma unroll
        for (int j = 0; j < TN; j++) {
            int n = n0 + tx * TN + j;
            float v = acc[i][j];
            if (MODE == 2) v = fmaxf(v + bias[n], 0.f);
            C[(size_t)m * ldc + n] = v;
        }
    }
}

__global__ void head2_kernel(const float* __restrict__ hid,
                             const float* __restrict__ W2,
                             const float* __restrict__ b2,
                             float* __restrict__ out)
{
    __shared__ float red[256];
    int b = blockIdx.x;
    float s = 0.f;
    for (int i = threadIdx.x; i < 2 * H_SZ; i += 256)
        s += hid[(size_t)b * 2 * H_SZ + i] * W2[i];
    red[threadIdx.x] = s;
    __syncthreads();
    for (int off = 128; off > 0; off >>= 1) {
        if (threadIdx.x < off) red[threadIdx.x] += red[threadIdx.x + off];
        __syncthreads();
    }
    if (threadIdx.x == 0) out[b] = red[0] + b2[0];
}

// ---------------- host ----------------
extern "C" void kernel_launch(void* const* d_in, const int* in_sizes, int n_in,
                              void* d_out, int out_size)
{
    const int*   x       = (const int*)  d_in[0];
    const float* embed_W = (const float*)d_in[1];
    const float* W_ih    = (const float*)d_in[2];
    const float* b_ih    = (const float*)d_in[3];
    const float* W1      = (const float*)d_in[4];
    const float* b1      = (const float*)d_in[5];
    const float* W2      = (const float*)d_in[6];
    const float* b2      = (const float*)d_in[7];
    float*       out     = (float*)d_out;

    float *table, *hlast, *hid, *part;
    int* cnt;
    __nv_bfloat16 *hhi0, *hhi1, *hlo0, *hlo1, *whi, *wlo;
    cudaGetSymbolAddress((void**)&table, g_table);
    cudaGetSymbolAddress((void**)&hlast, g_hlast);
    cudaGetSymbolAddress((void**)&hid,   g_hid);
    cudaGetSymbolAddress((void**)&part,  g_part);
    cudaGetSymbolAddress((void**)&cnt,   g_cnt);
    {
        __nv_bfloat16* p;
        cudaGetSymbolAddress((void**)&p, g_h_hi); hhi0 = p; hhi1 = p + B_SZ * H_SZ;
        cudaGetSymbolAddress((void**)&p, g_h_lo); hlo0 = p; hlo1 = p + B_SZ * H_SZ;
        cudaGetSymbolAddress((void**)&p, g_w_hi); whi = p;
        cudaGetSymbolAddress((void**)&p, g_w_lo); wlo = p;
    }

    // h0 = 0 (buffer 0), counters = 0
    zero_h_kernel<<<(B_SZ * H_SZ) / 256, 256>>>(hhi0, hlo0, cnt);
    // split W_h into bf16 hi/lo
    split_w_kernel<<<(H_SZ * H_SZ) / 256, 256>>>(W_ih, whi, wlo);
    // vocab table: T[v,j] = embed_W[v,:] . W_e[j,:]
    gemm_nt<64, 64, 32, 4, 4, 0, true>
        <<<dim3(H_SZ / 64, (V_SZ + 63) / 64), 256>>>(
            embed_W, E_SZ, W_ih, E_SZ + H_SZ, table, H_SZ,
            V_SZ, H_SZ, E_SZ, nullptr);

    // 512 recurrence steps (tensor cores, split-K x2)
    for (int t = 0; t < S_SZ; t++) {
        int ib = t & 1;
        const __nv_bfloat16* ihi = ib ? hhi1 : hhi0;
        const __nv_bfloat16* ilo = ib ? hlo1 : hlo0;
        __nv_bfloat16* ohi = ib ? hhi0 : hhi1;
        __nv_bfloat16* olo = ib ? hlo0 : hlo1;
        step_kernel<<<dim3(2, H_SZ / 64, B_SZ / 32), 128>>>(
            ihi, ilo, whi, wlo, table, b_ih, x, t, ohi, olo, part, cnt);
    }

    // h_last lives in buffer 0 (512 even steps)
    recon_h_kernel<<<(B_SZ * H_SZ) / 256, 256>>>(hhi0, hlo0, hlast);

    gemm_nt<64, 64, 32, 4, 4, 2, false>
        <<<dim3(2 * H_SZ / 64, B_SZ / 64), 256>>>(
            hlast, H_SZ, W1, H_SZ, hid, 2 * H_SZ,
            B_SZ, 2 * H_SZ, H_SZ, b1);

    head2_kernel<<<B_SZ, 256>>>(hid, W2, b2, out);
}

// round 5
// speedup vs baseline: 3.4766x; 1.2252x over previous
#include <cuda_runtime.h>
#include <cuda_bf16.h>
#include <math.h>
#include <stdint.h>

#define B_SZ 256
#define S_SZ 512
#define V_SZ 50000
#define E_SZ 300
#define H_SZ 1024

// persistent-kernel tiling: 4 mtiles(64) x 8 ntiles(128) x 4 kq(256) = 128 CTAs
#define NCTA     128
#define MT       64
#define NTN      128
#define KQ       256
#define NCHUNK   8            // KQ/32
#define NSTAGE   4

// smem: W [2 term][8 ch][128 rows][64B] = 131072 ; h stages 4x[2][64][64B] = 32768
#define SW_BYTES   131072
#define HS_BYTES   32768
#define SMEM_TOTAL (SW_BYTES + HS_BYTES)

// ---------------- scratch ----------------
__device__ __align__(128) __nv_bfloat16 g_h_hi[2][B_SZ * H_SZ];
__device__ __align__(128) __nv_bfloat16 g_h_lo[2][B_SZ * H_SZ];
__device__ __align__(128) __nv_bfloat16 g_w_hi[H_SZ * H_SZ];
__device__ __align__(128) __nv_bfloat16 g_w_lo[H_SZ * H_SZ];
__device__ float g_table[(size_t)V_SZ * H_SZ];
__device__ float g_hlast[B_SZ * H_SZ];
__device__ float g_hid[B_SZ * 2 * H_SZ];
__device__ __align__(128) float g_part[32 * 4 * MT * NTN];   // [tile][kq][64][128]
__device__ int g_cnt[32];
__device__ int g_bar;

// ---------------- PTX helpers ----------------
__device__ __forceinline__ uint32_t smem_u32(const void* p) {
    return (uint32_t)__cvta_generic_to_shared(p);
}
__device__ __forceinline__ void cp16(uint32_t dst, const void* src) {
    asm volatile("cp.async.cg.shared.global [%0], [%1], 16;" :: "r"(dst), "l"(src));
}
#define CP_COMMIT() asm volatile("cp.async.commit_group;" ::: "memory")
#define CP_WAIT3()  asm volatile("cp.async.wait_group 3;" ::: "memory")
#define CP_WAIT0()  asm volatile("cp.async.wait_group 0;" ::: "memory")
__device__ __forceinline__ void l2pf(const void* p) {
    asm volatile("prefetch.global.L2 [%0];" :: "l"(p));
}
__device__ __forceinline__ void ldmx4(uint32_t* r, uint32_t addr) {
    asm volatile("ldmatrix.sync.aligned.m8n8.x4.shared.b16 {%0,%1,%2,%3}, [%4];"
        : "=r"(r[0]), "=r"(r[1]), "=r"(r[2]), "=r"(r[3]) : "r"(addr));
}
__device__ __forceinline__ void mma16816(float* d, const uint32_t* a,
                                         const uint32_t b0, const uint32_t b1) {
    asm volatile("mma.sync.aligned.m16n8k16.row.col.f32.bf16.bf16.f32 "
        "{%0,%1,%2,%3}, {%4,%5,%6,%7}, {%8,%9}, {%0,%1,%2,%3};"
        : "+f"(d[0]), "+f"(d[1]), "+f"(d[2]), "+f"(d[3])
        : "r"(a[0]), "r"(a[1]), "r"(a[2]), "r"(a[3]), "r"(b0), "r"(b1));
}

// ---------------- persistent RNN kernel ----------------
__global__ void __launch_bounds__(256, 1) rnn_kernel(
    const int* __restrict__ x,
    const float* __restrict__ bias)
{
    extern __shared__ __align__(128) char smem[];
    const uint32_t sw = smem_u32(smem);            // W region
    const uint32_t sh = sw + SW_BYTES;             // h stages

    const int tid  = threadIdx.x;
    const int lane = tid & 31;
    const int wid  = tid >> 5;
    const int wm   = wid >> 2;          // 0..1 -> m offset 32*wm
    const int wn   = wid & 3;           // 0..3 -> n offset 32*wn
    const int cta  = blockIdx.x;
    const int kq   = cta & 3;
    const int nidx = (cta >> 2) & 7;
    const int midx = cta >> 5;
    const int m0g  = midx * MT;
    const int n0g  = nidx * NTN;
    const int kbase = kq * KQ;
    const int tile = midx * 8 + nidx;

    // ---- load W slice into smem (once): 8192 16B units, 32/thread ----
    {
#pragma unroll
        for (int i = 0; i < 32; i++) {
            int u = tid + i * 256;
            int term = u >> 12;
            int v = u & 4095;
            int ch = v >> 9;
            int w2 = v & 511;
            int r = w2 >> 2, c = w2 & 3;
            const __nv_bfloat16* src = (term ? g_w_lo : g_w_hi)
                + (size_t)(n0g + r) * H_SZ + kbase + ch * 32 + c * 8;
            uint32_t dst = sw + term * 65536 + ch * 8192 + r * 64
                         + ((c ^ ((r >> 1) & 3)) << 4);
            cp16(dst, src);
        }
        CP_COMMIT(); CP_WAIT0();
        __syncthreads();
    }

    // ---- ldmatrix lane geometry ----
    const int rA0 = wm * 32 + (lane & 15);
    const int rA1 = rA0 + 16;
    const int cAadd = lane >> 4;
    const int swzA = (rA0 >> 1) & 3;                 // same for rA1 (+16)
    const int rowB0 = wn * 32 + ((lane >> 4) << 3) + (lane & 7);
    const int rowB1 = rowB0 + 16;
    const int cBadd = (lane >> 3) & 1;
    const int swzB0 = (rowB0 >> 1) & 3;              // same for rowB1

    // h-stage issue: 512 units, 2/thread
    auto issue_h = [&](const __nv_bfloat16* hhi_in, const __nv_bfloat16* hlo_in,
                       int stage, int ch) {
#pragma unroll
        for (int i = 0; i < 2; i++) {
            int u = tid + i * 256;
            int term = u >> 8;
            int v = u & 255;
            int r = v >> 2, c = v & 3;
            const __nv_bfloat16* src = (term ? hlo_in : hhi_in)
                + (size_t)(m0g + r) * H_SZ + kbase + ch * 32 + c * 8;
            uint32_t dst = sh + stage * 8192 + term * 4096 + r * 64
                         + ((c ^ ((r >> 1) & 3)) << 4);
            cp16(dst, src);
        }
        CP_COMMIT();
    };

    // ================= step loop =================
    for (int t = 0; t < S_SZ; t++) {
        const __nv_bfloat16* hhi_in = g_h_hi[t & 1];
        const __nv_bfloat16* hlo_in = g_h_lo[t & 1];
        __nv_bfloat16* hhi_out = g_h_hi[(t + 1) & 1];
        __nv_bfloat16* hlo_out = g_h_lo[(t + 1) & 1];

        // table L2 prefetch for my 16-row quarter (tokens independent of h)
        if (tid < 16) {
            int gr = m0g + kq * 16 + tid;
            int tok = x[(size_t)gr * S_SZ + t];
            const char* p = (const char*)(g_table + (size_t)tok * H_SZ + n0g);
            l2pf(p); l2pf(p + 128); l2pf(p + 256); l2pf(p + 384);
        }

        // prologue: fill 4 stages (chunks 0..3)
        issue_h(hhi_in, hlo_in, 0, 0);
        issue_h(hhi_in, hlo_in, 1, 1);
        issue_h(hhi_in, hlo_in, 2, 2);
        issue_h(hhi_in, hlo_in, 3, 3);

        float acc[2][4][4];
#pragma unroll
        for (int i = 0; i < 2; i++)
#pragma unroll
            for (int j = 0; j < 4; j++)
#pragma unroll
                for (int q = 0; q < 4; q++) acc[i][j][q] = 0.f;

        for (int ch = 0; ch < NCHUNK; ch++) {
            CP_WAIT3();
            __syncthreads();
            const uint32_t hst = sh + (ch & 3) * 8192;
            const uint32_t wst = sw + ch * 8192;
#pragma unroll
            for (int kk = 0; kk < 2; kk++) {
                const int cA  = ((kk * 2 + cAadd) ^ swzA) << 4;
                const int cB  = ((kk * 2 + cBadd) ^ swzB0) << 4;
                uint32_t ahi[8], alo[8], bhi[8], blo[8];
                ldmx4(ahi,     hst + rA0 * 64 + cA);
                ldmx4(ahi + 4, hst + rA1 * 64 + cA);
                ldmx4(alo,     hst + 4096 + rA0 * 64 + cA);
                ldmx4(alo + 4, hst + 4096 + rA1 * 64 + cA);
                ldmx4(bhi,     wst + rowB0 * 64 + cB);
                ldmx4(bhi + 4, wst + rowB1 * 64 + cB);
                ldmx4(blo,     wst + 65536 + rowB0 * 64 + cB);
                ldmx4(blo + 4, wst + 65536 + rowB1 * 64 + cB);
#pragma unroll
                for (int i = 0; i < 2; i++)
#pragma unroll
                    for (int j = 0; j < 4; j++) {
                        const uint32_t* bh = &bhi[(j >> 1) * 4 + (j & 1) * 2];
                        const uint32_t* bl = &blo[(j >> 1) * 4 + (j & 1) * 2];
                        mma16816(acc[i][j], ahi + i * 4, bh[0], bh[1]);
                        mma16816(acc[i][j], ahi + i * 4, bl[0], bl[1]);
                        mma16816(acc[i][j], alo + i * 4, bh[0], bh[1]);
                    }
            }
            __syncthreads();
            if (ch + NSTAGE < NCHUNK) issue_h(hhi_in, hlo_in, ch & 3, ch + NSTAGE);
            else CP_COMMIT();                 // keep 12 groups/step invariant
        }

        // ---- write my partial (row-major [64][128] fp32) ----
        {
            float* pb = g_part + ((size_t)tile * 4 + kq) * (MT * NTN);
#pragma unroll
            for (int i = 0; i < 2; i++) {
                const int r = wm * 32 + i * 16 + (lane >> 2);
#pragma unroll
                for (int j = 0; j < 4; j++) {
                    const int c = wn * 32 + j * 8 + 2 * (lane & 3);
                    *reinterpret_cast<float2*>(pb + r * NTN + c) =
                        make_float2(acc[i][j][0], acc[i][j][1]);
                    *reinterpret_cast<float2*>(pb + (r + 8) * NTN + c) =
                        make_float2(acc[i][j][2], acc[i][j][3]);
                }
            }
        }
        __threadfence();
        __syncthreads();
        if (tid == 0) {
            atomicAdd(&g_cnt[tile], 1);
            const int tgt = 4 * (t + 1);
            while (*(volatile int*)&g_cnt[tile] < tgt) __nanosleep(32);
            __threadfence();
        }
        __syncthreads();

        // ---- reduce my 16-row quarter + epilogue ----
        {
            const int rloc = tid >> 4;                 // 0..15
            const int c0   = (tid & 15) * 8;           // 0..120
            const int pr   = kq * 16 + rloc;           // row within tile
            const int gr   = m0g + pr;                 // global batch row
            const float* pb = g_part + (size_t)tile * 4 * (MT * NTN)
                            + pr * NTN + c0;
            float4 s0 = make_float4(0.f, 0.f, 0.f, 0.f);
            float4 s1 = s0;
#pragma unroll
            for (int q = 0; q < 4; q++) {              // fixed order: deterministic
                const float4* p = reinterpret_cast<const float4*>(pb + q * (MT * NTN));
                float4 a = p[0], b = p[1];
                s0.x += a.x; s0.y += a.y; s0.z += a.z; s0.w += a.w;
                s1.x += b.x; s1.y += b.y; s1.z += b.z; s1.w += b.w;
            }
            const int tok = x[(size_t)gr * S_SZ + t];
            const float4* tv = reinterpret_cast<const float4*>(
                g_table + (size_t)tok * H_SZ + n0g + c0);
            const float4* bv = reinterpret_cast<const float4*>(bias + n0g + c0);
            float4 t0 = tv[0], t1 = tv[1], b0 = bv[0], b1 = bv[1];
            float v[8];
            v[0] = tanhf(s0.x + t0.x + b0.x);
            v[1] = tanhf(s0.y + t0.y + b0.y);
            v[2] = tanhf(s0.z + t0.z + b0.z);
            v[3] = tanhf(s0.w + t0.w + b0.w);
            v[4] = tanhf(s1.x + t1.x + b1.x);
            v[5] = tanhf(s1.y + t1.y + b1.y);
            v[6] = tanhf(s1.z + t1.z + b1.z);
            v[7] = tanhf(s1.w + t1.w + b1.w);
            __nv_bfloat16 hi8[8], lo8[8];
#pragma unroll
            for (int q = 0; q < 8; q++) {
                hi8[q] = __float2bfloat16(v[q]);
                lo8[q] = __float2bfloat16(v[q] - __bfloat162float(hi8[q]));
            }
            const size_t ob = (size_t)gr * H_SZ + n0g + c0;
            *reinterpret_cast<uint4*>(hhi_out + ob) = *reinterpret_cast<uint4*>(hi8);
            *reinterpret_cast<uint4*>(hlo_out + ob) = *reinterpret_cast<uint4*>(lo8);
        }

        // ---- grid barrier (skip after final step) ----
        if (t + 1 < S_SZ) {
            __threadfence();
            __syncthreads();
            if (tid == 0) {
                atomicAdd(&g_bar, 1);
                const int tgt = NCTA * (t + 1);
                while (*(volatile int*)&g_bar < tgt) __nanosleep(32);
                __threadfence();
            }
            __syncthreads();
        }
    }
}

// ---------------- prep / misc ----------------
__global__ void split_w_kernel(const float* __restrict__ W_ih,
                               __nv_bfloat16* __restrict__ whi,
                               __nv_bfloat16* __restrict__ wlo)
{
    int i = blockIdx.x * 256 + threadIdx.x;
    int j = i >> 10, k = i & (H_SZ - 1);
    float w = W_ih[(size_t)j * (E_SZ + H_SZ) + E_SZ + k];
    __nv_bfloat16 hi = __float2bfloat16(w);
    whi[i] = hi;
    wlo[i] = __float2bfloat16(w - __bfloat162float(hi));
}

__global__ void init_kernel(__nv_bfloat16* hi, __nv_bfloat16* lo,
                            int* cnt, int* bar) {
    int i = blockIdx.x * 256 + threadIdx.x;
    hi[i] = __float2bfloat16(0.f);
    lo[i] = __float2bfloat16(0.f);
    if (i < 32) cnt[i] = 0;
    if (i == 0) *bar = 0;
}

__global__ void recon_h_kernel(const __nv_bfloat16* __restrict__ hi,
                               const __nv_bfloat16* __restrict__ lo,
                               float* __restrict__ out) {
    int i = blockIdx.x * 256 + threadIdx.x;
    out[i] = __bfloat162float(hi[i]) + __bfloat162float(lo[i]);
}

// ---------------- SIMT GEMM (table precompute + MLP L1) ----------------
template<int BM, int BN, int BK, int TM, int TN, int MODE, bool GUARD>
__global__ void __launch_bounds__(256) gemm_nt(
    const float* __restrict__ A, int lda,
    const float* __restrict__ B, int ldb,
    float* __restrict__ C, int ldc,
    int M, int N, int K,
    const float* __restrict__ bias)
{
    constexpr int BNP = BN + 1;
    __shared__ float As[BM * BK];
    __shared__ float Bs[BK * BNP];
    const int tid = threadIdx.x;
    const int tx = tid % (BN / TN);
    const int ty = tid / (BN / TN);
    const int m0 = blockIdx.y * BM;
    const int n0 = blockIdx.x * BN;
    constexpr int A_LD = (BM * BK / 4) / 256;
    constexpr int B_LD = (BN * BK / 4) / 256;
    float4 aReg[A_LD], bReg[B_LD];
    const int KT = (K + BK - 1) / BK;

    auto loadA = [&](int kt) {
#pragma unroll
        for (int i = 0; i < A_LD; i++) {
            int idx = tid + i * 256;
            int r = idx / (BK / 4), c4 = idx % (BK / 4);
            int gm = m0 + r, gk = kt * BK + c4 * 4;
            if (!GUARD) aReg[i] = *reinterpret_cast<const float4*>(&A[(size_t)gm * lda + gk]);
            else {
                float4 v = make_float4(0.f, 0.f, 0.f, 0.f);
                if (gm < M) {
                    const float* p = &A[(size_t)gm * lda + gk];
                    if (gk + 0 < K) v.x = p[0];
                    if (gk + 1 < K) v.y = p[1];
                    if (gk + 2 < K) v.z = p[2];
                    if (gk + 3 < K) v.w = p[3];
                }
                aReg[i] = v;
            }
        }
    };
    auto loadB = [&](int kt) {
#pragma unroll
        for (int i = 0; i < B_LD; i++) {
            int idx = tid + i * 256;
            int r = idx / (BK / 4), c4 = idx % (BK / 4);
            int gn = n0 + r, gk = kt * BK + c4 * 4;
            if (!GUARD) bReg[i] = *reinterpret_cast<const float4*>(&B[(size_t)gn * ldb + gk]);
            else {
                float4 v = make_float4(0.f, 0.f, 0.f, 0.f);
                const float* p = &B[(size_t)gn * ldb + gk];
                if (gk + 0 < K) v.x = p[0];
                if (gk + 1 < K) v.y = p[1];
                if (gk + 2 < K) v.z = p[2];
                if (gk + 3 < K) v.w = p[3];
                bReg[i] = v;
            }
        }
    };
    auto storeA = [&]() {
#pragma unroll
        for (int i = 0; i < A_LD; i++) {
            int idx = tid + i * 256;
            int r = idx / (BK / 4), c4 = idx % (BK / 4);
            *reinterpret_cast<float4*>(&As[r * BK + c4 * 4]) = aReg[i];
        }
    };
    auto storeB = [&]() {
#pragma unroll
        for (int i = 0; i < B_LD; i++) {
            int idx = tid + i * 256;
            int r = idx / (BK / 4), c4 = idx % (BK / 4);
            int kb = c4 * 4;
            float4 v = bReg[i];
            Bs[(kb + 0) * BNP + r] = v.x;
            Bs[(kb + 1) * BNP + r] = v.y;
            Bs[(kb + 2) * BNP + r] = v.z;
            Bs[(kb + 3) * BNP + r] = v.w;
        }
    };

    float acc[TM][TN];
#pragma unroll
    for (int i = 0; i < TM; i++)
#pragma unroll
        for (int j = 0; j < TN; j++) acc[i][j] = 0.f;

    loadA(0); loadB(0); storeA(); storeB();
    __syncthreads();
    for (int kt = 0; kt < KT; kt++) {
        if (kt + 1 < KT) { loadA(kt + 1); loadB(kt + 1); }
#pragma unroll
        for (int kk = 0; kk < BK; kk++) {
            float a[TM], b[TN];
#pragma unroll
            for (int i = 0; i < TM; i++) a[i] = As[(ty * TM + i) * BK + kk];
#pragma unroll
            for (int j = 0; j < TN; j++) b[j] = Bs[kk * BNP + tx * TN + j];
#pragma unroll
            for (int i = 0; i < TM; i++)
#pragma unroll
                for (int j = 0; j < TN; j++)
                    acc[i][j] = fmaf(a[i], b[j], acc[i][j]);
        }
        __syncthreads();
        if (kt + 1 < KT) { storeA(); storeB(); }
        __syncthreads();
    }
#pragma unroll
    for (int i = 0; i < TM; i++) {
        int m = m0 + ty * TM + i;
        if (GUARD && m >= M) continue;
#pragma unroll
        for (int j = 0; j < TN; j++) {
            int n = n0 + tx * TN + j;
            float v = acc[i][j];
            if (MODE == 2) v = fmaxf(v + bias[n], 0.f);
            C[(size_t)m * ldc + n] = v;
        }
    }
}

__global__ void head2_kernel(const float* __restrict__ hid,
                             const float* __restrict__ W2,
                             const float* __restrict__ b2,
                             float* __restrict__ out)
{
    __shared__ float red[256];
    int b = blockIdx.x;
    float s = 0.f;
    for (int i = threadIdx.x; i < 2 * H_SZ; i += 256)
        s += hid[(size_t)b * 2 * H_SZ + i] * W2[i];
    red[threadIdx.x] = s;
    __syncthreads();
    for (int off = 128; off > 0; off >>= 1) {
        if (threadIdx.x < off) red[threadIdx.x] += red[threadIdx.x + off];
        __syncthreads();
    }
    if (threadIdx.x == 0) out[b] = red[0] + b2[0];
}

// ---------------- host ----------------
extern "C" void kernel_launch(void* const* d_in, const int* in_sizes, int n_in,
                              void* d_out, int out_size)
{
    const int*   x       = (const int*)  d_in[0];
    const float* embed_W = (const float*)d_in[1];
    const float* W_ih    = (const float*)d_in[2];
    const float* b_ih    = (const float*)d_in[3];
    const float* W1      = (const float*)d_in[4];
    const float* b1      = (const float*)d_in[5];
    const float* W2      = (const float*)d_in[6];
    const float* b2      = (const float*)d_in[7];
    float*       out     = (float*)d_out;

    float *table, *hlast, *hid;
    int *cnt, *bar;
    __nv_bfloat16 *hhi0, *hlo0, *whi, *wlo;
    cudaGetSymbolAddress((void**)&table, g_table);
    cudaGetSymbolAddress((void**)&hlast, g_hlast);
    cudaGetSymbolAddress((void**)&hid,   g_hid);
    cudaGetSymbolAddress((void**)&cnt,   g_cnt);
    cudaGetSymbolAddress((void**)&bar,   g_bar);
    {
        __nv_bfloat16* p;
        cudaGetSymbolAddress((void**)&p, g_h_hi); hhi0 = p;
        cudaGetSymbolAddress((void**)&p, g_h_lo); hlo0 = p;
        cudaGetSymbolAddress((void**)&p, g_w_hi); whi = p;
        cudaGetSymbolAddress((void**)&p, g_w_lo); wlo = p;
    }

    static bool attr_done = false;
    if (!attr_done) {
        cudaFuncSetAttribute(rnn_kernel,
            cudaFuncAttributeMaxDynamicSharedMemorySize, SMEM_TOTAL);
        attr_done = true;
    }

    // h0 = 0 (buffer 0), barrier/tile counters = 0
    init_kernel<<<(B_SZ * H_SZ) / 256, 256>>>(hhi0, hlo0, cnt, bar);
    // split W_h into bf16 hi/lo
    split_w_kernel<<<(H_SZ * H_SZ) / 256, 256>>>(W_ih, whi, wlo);
    // vocab table: T[v,j] = embed_W[v,:] . W_e[j,:]
    gemm_nt<64, 64, 32, 4, 4, 0, true>
        <<<dim3(H_SZ / 64, (V_SZ + 63) / 64), 256>>>(
            embed_W, E_SZ, W_ih, E_SZ + H_SZ, table, H_SZ,
            V_SZ, H_SZ, E_SZ, nullptr);

    // all 512 recurrence steps in ONE persistent kernel
    rnn_kernel<<<NCTA, 256, SMEM_TOTAL>>>(x, b_ih);

    // h_last = dbuf[0] after 512 steps
    recon_h_kernel<<<(B_SZ * H_SZ) / 256, 256>>>(hhi0,
        (const __nv_bfloat16*)((char*)0 + 0) == nullptr ? hhi0 : hhi0, hlast);
    // NOTE: recon uses hi+lo of buffer 0:
    {
        __nv_bfloat16 *plo;
        cudaGetSymbolAddress((void**)&plo, g_h_lo);
        recon_h_kernel<<<(B_SZ * H_SZ) / 256, 256>>>(hhi0, plo, hlast);
    }

    gemm_nt<64, 64, 32, 4, 4, 2, false>
        <<<dim3(2 * H_SZ / 64, B_SZ / 64), 256>>>(
            hlast, H_SZ, W1, H_SZ, hid, 2 * H_SZ,
            B_SZ, 2 * H_SZ, H_SZ, b1);

    head2_kernel<<<B_SZ, 256>>>(hid, W2, b2, out);
}

// round 6
// speedup vs baseline: 3.8503x; 1.1075x over previous
#include <cuda_runtime.h>
#include <cuda_bf16.h>
#include <math.h>
#include <stdint.h>

#define B_SZ 256
#define S_SZ 512
#define V_SZ 50000
#define E_SZ 300
#define H_SZ 1024
#define KP   320          // K padded for table GEMM (300 -> 320)

// persistent-kernel tiling: 4 mtiles(64) x 8 ntiles(128) x 4 kq(256) = 128 CTAs
#define NCTA     128
#define MT       64
#define NTN      128
#define KQ       256
#define NCHUNK   8
#define NSTAGE   4
#define SW_BYTES   131072
#define HS_BYTES   32768
#define SMEM_RNN   (SW_BYTES + HS_BYTES)

// table kernel: tile 128M x 64N, K=320 (10 chunks of 32), 3 stages x 24KB
#define TB_STG   24576
#define SMEM_TAB (3 * TB_STG)

// ---------------- scratch ----------------
__device__ __align__(128) __nv_bfloat16 g_h_hi[2][B_SZ * H_SZ];
__device__ __align__(128) __nv_bfloat16 g_h_lo[2][B_SZ * H_SZ];
__device__ __align__(128) __nv_bfloat16 g_w_hi[H_SZ * H_SZ];
__device__ __align__(128) __nv_bfloat16 g_w_lo[H_SZ * H_SZ];
__device__ __align__(128) __nv_bfloat16 g_e_hi[(size_t)V_SZ * KP];
__device__ __align__(128) __nv_bfloat16 g_e_lo[(size_t)V_SZ * KP];
__device__ __align__(128) __nv_bfloat16 g_we_hi[H_SZ * KP];
__device__ __align__(128) __nv_bfloat16 g_we_lo[H_SZ * KP];
__device__ float g_table[(size_t)V_SZ * H_SZ];
__device__ float g_hlast[B_SZ * H_SZ];
__device__ float g_hid[B_SZ * 2 * H_SZ];
__device__ __align__(128) float g_part[32 * 4 * MT * NTN];
__device__ int g_cnt[32];
__device__ int g_bar;

// ---------------- PTX helpers ----------------
__device__ __forceinline__ uint32_t smem_u32(const void* p) {
    return (uint32_t)__cvta_generic_to_shared(p);
}
__device__ __forceinline__ void cp16(uint32_t dst, const void* src) {
    asm volatile("cp.async.cg.shared.global [%0], [%1], 16;" :: "r"(dst), "l"(src));
}
#define CP_COMMIT() asm volatile("cp.async.commit_group;" ::: "memory")
#define CP_WAIT_G3() asm volatile("cp.async.wait_group 3;" ::: "memory")
#define CP_WAIT_G2() asm volatile("cp.async.wait_group 2;" ::: "memory")
#define CP_WAIT_G0() asm volatile("cp.async.wait_group 0;" ::: "memory")
__device__ __forceinline__ void l2pf(const void* p) {
    asm volatile("prefetch.global.L2 [%0];" :: "l"(p));
}
__device__ __forceinline__ void ldmx4(uint32_t* r, uint32_t addr) {
    asm volatile("ldmatrix.sync.aligned.m8n8.x4.shared.b16 {%0,%1,%2,%3}, [%4];"
        : "=r"(r[0]), "=r"(r[1]), "=r"(r[2]), "=r"(r[3]) : "r"(addr));
}
__device__ __forceinline__ void mma16816(float* d, const uint32_t* a,
                                         const uint32_t b0, const uint32_t b1) {
    asm volatile("mma.sync.aligned.m16n8k16.row.col.f32.bf16.bf16.f32 "
        "{%0,%1,%2,%3}, {%4,%5,%6,%7}, {%8,%9}, {%0,%1,%2,%3};"
        : "+f"(d[0]), "+f"(d[1]), "+f"(d[2]), "+f"(d[3])
        : "r"(a[0]), "r"(a[1]), "r"(a[2]), "r"(a[3]), "r"(b0), "r"(b1));
}

// ---------------- persistent RNN kernel (512 threads, 16 warps) ----------------
__global__ void __launch_bounds__(512, 1) rnn_kernel(
    const int* __restrict__ x,
    const float* __restrict__ bias)
{
    extern __shared__ __align__(128) char smem[];
    const uint32_t sw = smem_u32(smem);
    const uint32_t sh = sw + SW_BYTES;

    const int tid  = threadIdx.x;
    const int lane = tid & 31;
    const int wid  = tid >> 5;          // 0..15
    const int wm   = wid >> 2;          // 0..3 -> 16-row band
    const int wn   = wid & 3;           // 0..3 -> 32-col band
    const int cta  = blockIdx.x;
    const int kq   = cta & 3;
    const int nidx = (cta >> 2) & 7;
    const int midx = cta >> 5;
    const int m0g  = midx * MT;
    const int n0g  = nidx * NTN;
    const int kbase = kq * KQ;
    const int tile = midx * 8 + nidx;

    // ---- load W slice into smem once: 8192 16B units, 16/thread ----
    {
#pragma unroll
        for (int i = 0; i < 16; i++) {
            int u = tid + i * 512;
            int term = u >> 12;
            int v = u & 4095;
            int ch = v >> 9;
            int w2 = v & 511;
            int r = w2 >> 2, c = w2 & 3;
            const __nv_bfloat16* src = (term ? g_w_lo : g_w_hi)
                + (size_t)(n0g + r) * H_SZ + kbase + ch * 32 + c * 8;
            uint32_t dst = sw + term * 65536 + ch * 8192 + r * 64
                         + ((c ^ ((r >> 1) & 3)) << 4);
            cp16(dst, src);
        }
        CP_COMMIT(); CP_WAIT_G0();
        __syncthreads();
    }

    // ldmatrix lane geometry (warp tile 16M x 32N)
    const int rA = wm * 16 + (lane & 15);
    const int cAadd = lane >> 4;
    const int swzA = (rA >> 1) & 3;
    const int rowB0 = wn * 32 + ((lane >> 4) << 3) + (lane & 7);
    const int rowB1 = rowB0 + 16;
    const int cBadd = (lane >> 3) & 1;
    const int swzB = (rowB0 >> 1) & 3;

    // h-stage issue: 512 units, 1/thread
    auto issue_h = [&](const __nv_bfloat16* hhi_in, const __nv_bfloat16* hlo_in,
                       int stage, int ch) {
        int u = tid;
        int term = u >> 8;
        int v = u & 255;
        int r = v >> 2, c = v & 3;
        const __nv_bfloat16* src = (term ? hlo_in : hhi_in)
            + (size_t)(m0g + r) * H_SZ + kbase + ch * 32 + c * 8;
        uint32_t dst = sh + stage * 8192 + term * 4096 + r * 64
                     + ((c ^ ((r >> 1) & 3)) << 4);
        cp16(dst, src);
        CP_COMMIT();
    };

    for (int t = 0; t < S_SZ; t++) {
        const __nv_bfloat16* hhi_in = g_h_hi[t & 1];
        const __nv_bfloat16* hlo_in = g_h_lo[t & 1];
        __nv_bfloat16* hhi_out = g_h_hi[(t + 1) & 1];
        __nv_bfloat16* hlo_out = g_h_lo[(t + 1) & 1];

        // table L2 prefetch for my 16-row quarter
        if (tid < 16) {
            int gr = m0g + kq * 16 + tid;
            int tok = x[(size_t)gr * S_SZ + t];
            const char* p = (const char*)(g_table + (size_t)tok * H_SZ + n0g);
            l2pf(p); l2pf(p + 128); l2pf(p + 256); l2pf(p + 384);
        }

        issue_h(hhi_in, hlo_in, 0, 0);
        issue_h(hhi_in, hlo_in, 1, 1);
        issue_h(hhi_in, hlo_in, 2, 2);
        issue_h(hhi_in, hlo_in, 3, 3);

        float acc[4][4];
#pragma unroll
        for (int j = 0; j < 4; j++)
#pragma unroll
            for (int q = 0; q < 4; q++) acc[j][q] = 0.f;

        for (int ch = 0; ch < NCHUNK; ch++) {
            CP_WAIT_G3();
            __syncthreads();
            const uint32_t hst = sh + (ch & 3) * 8192;
            const uint32_t wst = sw + ch * 8192;
#pragma unroll
            for (int kk = 0; kk < 2; kk++) {
                const int cA = ((kk * 2 + cAadd) ^ swzA) << 4;
                const int cB = ((kk * 2 + cBadd) ^ swzB) << 4;
                uint32_t ahi[4], alo[4], bhi[8], blo[8];
                ldmx4(ahi, hst + rA * 64 + cA);
                ldmx4(alo, hst + 4096 + rA * 64 + cA);
                ldmx4(bhi,     wst + rowB0 * 64 + cB);
                ldmx4(bhi + 4, wst + rowB1 * 64 + cB);
                ldmx4(blo,     wst + 65536 + rowB0 * 64 + cB);
                ldmx4(blo + 4, wst + 65536 + rowB1 * 64 + cB);
                // term-outer: dependent MMAs on one acc are 4 apart
#pragma unroll
                for (int j = 0; j < 4; j++) {
                    const uint32_t* b = &bhi[(j >> 1) * 4 + (j & 1) * 2];
                    mma16816(acc[j], ahi, b[0], b[1]);
                }
#pragma unroll
                for (int j = 0; j < 4; j++) {
                    const uint32_t* b = &blo[(j >> 1) * 4 + (j & 1) * 2];
                    mma16816(acc[j], ahi, b[0], b[1]);
                }
#pragma unroll
                for (int j = 0; j < 4; j++) {
                    const uint32_t* b = &bhi[(j >> 1) * 4 + (j & 1) * 2];
                    mma16816(acc[j], alo, b[0], b[1]);
                }
            }
            __syncthreads();
            if (ch + NSTAGE < NCHUNK) issue_h(hhi_in, hlo_in, ch & 3, ch + NSTAGE);
            else CP_COMMIT();
        }

        // ---- write my partial (row-major [64][128] fp32) ----
        {
            float* pb = g_part + ((size_t)tile * 4 + kq) * (MT * NTN);
            const int r = wm * 16 + (lane >> 2);
#pragma unroll
            for (int j = 0; j < 4; j++) {
                const int c = wn * 32 + j * 8 + 2 * (lane & 3);
                *reinterpret_cast<float2*>(pb + r * NTN + c) =
                    make_float2(acc[j][0], acc[j][1]);
                *reinterpret_cast<float2*>(pb + (r + 8) * NTN + c) =
                    make_float2(acc[j][2], acc[j][3]);
            }
        }
        __threadfence();
        __syncthreads();
        if (tid == 0) {
            atomicAdd(&g_cnt[tile], 1);
            const int tgt = 4 * (t + 1);
            while (*(volatile int*)&g_cnt[tile] < tgt) __nanosleep(32);
            __threadfence();
        }
        __syncthreads();

        // ---- reduce my 16-row quarter + epilogue (512 thr x 4 cols) ----
        {
            const int rloc = tid >> 5;                 // 0..15
            const int c0   = lane * 4;                 // 0..124
            const int pr   = kq * 16 + rloc;
            const int gr   = m0g + pr;
            const float* pb = g_part + (size_t)tile * 4 * (MT * NTN)
                            + pr * NTN + c0;
            float4 s = make_float4(0.f, 0.f, 0.f, 0.f);
#pragma unroll
            for (int q = 0; q < 4; q++) {              // fixed order: deterministic
                float4 a = *reinterpret_cast<const float4*>(pb + q * (MT * NTN));
                s.x += a.x; s.y += a.y; s.z += a.z; s.w += a.w;
            }
            const int tok = x[(size_t)gr * S_SZ + t];
            float4 tv = *reinterpret_cast<const float4*>(
                g_table + (size_t)tok * H_SZ + n0g + c0);
            float4 bv = *reinterpret_cast<const float4*>(bias + n0g + c0);
            float v0 = tanhf(s.x + tv.x + bv.x);
            float v1 = tanhf(s.y + tv.y + bv.y);
            float v2 = tanhf(s.z + tv.z + bv.z);
            float v3 = tanhf(s.w + tv.w + bv.w);
            __nv_bfloat16 h4[4], l4[4];
            h4[0] = __float2bfloat16(v0); l4[0] = __float2bfloat16(v0 - __bfloat162float(h4[0]));
            h4[1] = __float2bfloat16(v1); l4[1] = __float2bfloat16(v1 - __bfloat162float(h4[1]));
            h4[2] = __float2bfloat16(v2); l4[2] = __float2bfloat16(v2 - __bfloat162float(h4[2]));
            h4[3] = __float2bfloat16(v3); l4[3] = __float2bfloat16(v3 - __bfloat162float(h4[3]));
            const size_t ob = (size_t)gr * H_SZ + n0g + c0;
            *reinterpret_cast<uint2*>(hhi_out + ob) = *reinterpret_cast<uint2*>(h4);
            *reinterpret_cast<uint2*>(hlo_out + ob) = *reinterpret_cast<uint2*>(l4);
        }

        if (t + 1 < S_SZ) {
            __threadfence();
            __syncthreads();
            if (tid == 0) {
                atomicAdd(&g_bar, 1);
                const int tgt = NCTA * (t + 1);
                while (*(volatile int*)&g_bar < tgt) __nanosleep(32);
                __threadfence();
            }
            __syncthreads();
        }
    }
}

// ---------------- table GEMM on tensor cores ----------------
// T[v,n] = sum_k E[v,k] * W_e[n,k], bf16-split, K=320 (padded), tile 128x64.
__global__ void __launch_bounds__(256) table_mma_kernel()
{
    extern __shared__ __align__(128) char smem[];
    const uint32_t sb = smem_u32(smem);
    const int tid  = threadIdx.x;
    const int lane = tid & 31;
    const int wid  = tid >> 5;
    const int wm   = wid >> 1;          // 0..3 -> 32-row band
    const int wn   = wid & 1;           // 0..1 -> 32-col band
    const int n0   = blockIdx.x * 64;
    const int m0   = blockIdx.y * 128;

    auto issue_tab = [&](uint32_t sbase, int ch) {
#pragma unroll
        for (int i = 0; i < 6; i++) {
            int u = tid + i * 256;
            if (u < 1024) {                       // E tiles
                int term = u >> 9;
                int v = u & 511;
                int r = v >> 2, c = v & 3;
                int gm = m0 + r; if (gm >= V_SZ) gm = V_SZ - 1;
                const __nv_bfloat16* src = (term ? g_e_lo : g_e_hi)
                    + (size_t)gm * KP + ch * 32 + c * 8;
                uint32_t dst = sbase + term * 8192 + r * 64
                             + ((c ^ ((r >> 1) & 3)) << 4);
                cp16(dst, src);
            } else {                              // W_e tiles
                int v = u - 1024;
                int term = v >> 8;
                v &= 255;
                int r = v >> 2, c = v & 3;
                const __nv_bfloat16* src = (term ? g_we_lo : g_we_hi)
                    + (size_t)(n0 + r) * KP + ch * 32 + c * 8;
                uint32_t dst = sbase + 16384 + term * 4096 + r * 64
                             + ((c ^ ((r >> 1) & 3)) << 4);
                cp16(dst, src);
            }
        }
        CP_COMMIT();
    };

    issue_tab(sb + 0 * TB_STG, 0);
    issue_tab(sb + 1 * TB_STG, 1);
    issue_tab(sb + 2 * TB_STG, 2);

    const int rA0 = wm * 32 + (lane & 15);
    const int rA1 = rA0 + 16;
    const int cAadd = lane >> 4;
    const int swzA = (rA0 >> 1) & 3;
    const int rowB0 = wn * 32 + ((lane >> 4) << 3) + (lane & 7);
    const int rowB1 = rowB0 + 16;
    const int cBadd = (lane >> 3) & 1;
    const int swzB = (rowB0 >> 1) & 3;

    float acc[2][4][4];
#pragma unroll
    for (int i = 0; i < 2; i++)
#pragma unroll
        for (int j = 0; j < 4; j++)
#pragma unroll
            for (int q = 0; q < 4; q++) acc[i][j][q] = 0.f;

    const int NCH = KP / 32;                      // 10
    for (int ch = 0; ch < NCH; ch++) {
        CP_WAIT_G2();
        __syncthreads();
        const uint32_t st = sb + (ch % 3) * TB_STG;
#pragma unroll
        for (int kk = 0; kk < 2; kk++) {
            const int cA = ((kk * 2 + cAadd) ^ swzA) << 4;
            const int cB = ((kk * 2 + cBadd) ^ swzB) << 4;
            uint32_t ahi[8], alo[8], bhi[8], blo[8];
            ldmx4(ahi,     st + rA0 * 64 + cA);
            ldmx4(ahi + 4, st + rA1 * 64 + cA);
            ldmx4(alo,     st + 8192 + rA0 * 64 + cA);
            ldmx4(alo + 4, st + 8192 + rA1 * 64 + cA);
            ldmx4(bhi,     st + 16384 + rowB0 * 64 + cB);
            ldmx4(bhi + 4, st + 16384 + rowB1 * 64 + cB);
            ldmx4(blo,     st + 20480 + rowB0 * 64 + cB);
            ldmx4(blo + 4, st + 20480 + rowB1 * 64 + cB);
#pragma unroll
            for (int i = 0; i < 2; i++)
#pragma unroll
                for (int j = 0; j < 4; j++) {
                    const uint32_t* b = &bhi[(j >> 1) * 4 + (j & 1) * 2];
                    mma16816(acc[i][j], ahi + i * 4, b[0], b[1]);
                }
#pragma unroll
            for (int i = 0; i < 2; i++)
#pragma unroll
                for (int j = 0; j < 4; j++) {
                    const uint32_t* b = &blo[(j >> 1) * 4 + (j & 1) * 2];
                    mma16816(acc[i][j], ahi + i * 4, b[0], b[1]);
                }
#pragma unroll
            for (int i = 0; i < 2; i++)
#pragma unroll
                for (int j = 0; j < 4; j++) {
                    const uint32_t* b = &bhi[(j >> 1) * 4 + (j & 1) * 2];
                    mma16816(acc[i][j], alo + i * 4, b[0], b[1]);
                }
        }
        __syncthreads();
        if (ch + 3 < NCH) issue_tab(sb + (ch % 3) * TB_STG, ch + 3);
        else CP_COMMIT();
    }

    // epilogue: plain fp32 store (guard M)
#pragma unroll
    for (int i = 0; i < 2; i++) {
        const int r = wm * 32 + i * 16 + (lane >> 2);
#pragma unroll
        for (int j = 0; j < 4; j++) {
            const int c = wn * 32 + j * 8 + 2 * (lane & 3);
            int gm = m0 + r;
            if (gm < V_SZ)
                *reinterpret_cast<float2*>(g_table + (size_t)gm * H_SZ + n0 + c) =
                    make_float2(acc[i][j][0], acc[i][j][1]);
            if (gm + 8 < V_SZ)
                *reinterpret_cast<float2*>(g_table + (size_t)(gm + 8) * H_SZ + n0 + c) =
                    make_float2(acc[i][j][2], acc[i][j][3]);
        }
    }
}

// ---------------- prep / misc ----------------
__global__ void split_w_kernel(const float* __restrict__ W_ih,
                               __nv_bfloat16* __restrict__ whi,
                               __nv_bfloat16* __restrict__ wlo)
{
    int i = blockIdx.x * 256 + threadIdx.x;
    int j = i >> 10, k = i & (H_SZ - 1);
    float w = W_ih[(size_t)j * (E_SZ + H_SZ) + E_SZ + k];
    __nv_bfloat16 hi = __float2bfloat16(w);
    whi[i] = hi;
    wlo[i] = __float2bfloat16(w - __bfloat162float(hi));
}

__global__ void split_e_kernel(const float* __restrict__ embed_W)
{
    size_t id = (size_t)blockIdx.x * 256 + threadIdx.x;   // V*KP
    int row = (int)(id / KP);
    int col = (int)(id - (size_t)row * KP);
    float v = (col < E_SZ) ? embed_W[(size_t)row * E_SZ + col] : 0.f;
    __nv_bfloat16 hi = __float2bfloat16(v);
    g_e_hi[id] = hi;
    g_e_lo[id] = __float2bfloat16(v - __bfloat162float(hi));
}

__global__ void split_we_kernel(const float* __restrict__ W_ih)
{
    int id = blockIdx.x * 256 + threadIdx.x;              // H*KP
    int row = id / KP;
    int col = id - row * KP;
    float v = (col < E_SZ) ? W_ih[(size_t)row * (E_SZ + H_SZ) + col] : 0.f;
    __nv_bfloat16 hi = __float2bfloat16(v);
    g_we_hi[id] = hi;
    g_we_lo[id] = __float2bfloat16(v - __bfloat162float(hi));
}

__global__ void init_kernel(__nv_bfloat16* hi, __nv_bfloat16* lo,
                            int* cnt, int* bar) {
    int i = blockIdx.x * 256 + threadIdx.x;
    hi[i] = __float2bfloat16(0.f);
    lo[i] = __float2bfloat16(0.f);
    if (i < 32) cnt[i] = 0;
    if (i == 0) *bar = 0;
}

__global__ void recon_h_kernel(const __nv_bfloat16* __restrict__ hi,
                               const __nv_bfloat16* __restrict__ lo,
                               float* __restrict__ out) {
    int i = blockIdx.x * 256 + threadIdx.x;
    out[i] = __bfloat162float(hi[i]) + __bfloat162float(lo[i]);
}

// ---------------- SIMT GEMM (MLP L1 only) ----------------
template<int BM, int BN, int BK, int TM, int TN, int MODE, bool GUARD>
__global__ void __launch_bounds__(256) gemm_nt(
    const float* __restrict__ A, int lda,
    const float* __restrict__ B, int ldb,
    float* __restrict__ C, int ldc,
    int M, int N, int K,
    const float* __restrict__ bias)
{
    constexpr int BNP = BN + 1;
    __shared__ float As[BM * BK];
    __shared__ float Bs[BK * BNP];
    const int tid = threadIdx.x;
    const int tx = tid % (BN / TN);
    const int ty = tid / (BN / TN);
    const int m0 = blockIdx.y * BM;
    const int n0 = blockIdx.x * BN;
    constexpr int A_LD = (BM * BK / 4) / 256;
    constexpr int B_LD = (BN * BK / 4) / 256;
    float4 aReg[A_LD], bReg[B_LD];
    const int KT = (K + BK - 1) / BK;

    auto loadA = [&](int kt) {
#pragma unroll
        for (int i = 0; i < A_LD; i++) {
            int idx = tid + i * 256;
            int r = idx / (BK / 4), c4 = idx % (BK / 4);
            int gm = m0 + r, gk = kt * BK + c4 * 4;
            aReg[i] = *reinterpret_cast<const float4*>(&A[(size_t)gm * lda + gk]);
        }
    };
    auto loadB = [&](int kt) {
#pragma unroll
        for (int i = 0; i < B_LD; i++) {
            int idx = tid + i * 256;
            int r = idx / (BK / 4), c4 = idx % (BK / 4);
            int gn = n0 + r, gk = kt * BK + c4 * 4;
            bReg[i] = *reinterpret_cast<const float4*>(&B[(size_t)gn * ldb + gk]);
        }
    };
    auto storeA = [&]() {
#pragma unroll
        for (int i = 0; i < A_LD; i++) {
            int idx = tid + i * 256;
            int r = idx / (BK / 4), c4 = idx % (BK / 4);
            *reinterpret_cast<float4*>(&As[r * BK + c4 * 4]) = aReg[i];
        }
    };
    auto storeB = [&]() {
#pragma unroll
        for (int i = 0; i < B_LD; i++) {
            int idx = tid + i * 256;
            int r = idx / (BK / 4), c4 = idx % (BK / 4);
            int kb = c4 * 4;
            float4 v = bReg[i];
            Bs[(kb + 0) * BNP + r] = v.x;
            Bs[(kb + 1) * BNP + r] = v.y;
            Bs[(kb + 2) * BNP + r] = v.z;
            Bs[(kb + 3) * BNP + r] = v.w;
        }
    };

    float acc[TM][TN];
#pragma unroll
    for (int i = 0; i < TM; i++)
#pragma unroll
        for (int j = 0; j < TN; j++) acc[i][j] = 0.f;

    loadA(0); loadB(0); storeA(); storeB();
    __syncthreads();
    for (int kt = 0; kt < KT; kt++) {
        if (kt + 1 < KT) { loadA(kt + 1); loadB(kt + 1); }
#pragma unroll
        for (int kk = 0; kk < BK; kk++) {
            float a[TM], b[TN];
#pragma unroll
            for (int i = 0; i < TM; i++) a[i] = As[(ty * TM + i) * BK + kk];
#pragma unroll
            for (int j = 0; j < TN; j++) b[j] = Bs[kk * BNP + tx * TN + j];
#pragma unroll
            for (int i = 0; i < TM; i++)
#pragma unroll
                for (int j = 0; j < TN; j++)
                    acc[i][j] = fmaf(a[i], b[j], acc[i][j]);
        }
        __syncthreads();
        if (kt + 1 < KT) { storeA(); storeB(); }
        __syncthreads();
    }
#pragma unroll
    for (int i = 0; i < TM; i++) {
        int m = m0 + ty * TM + i;
#pragma unroll
        for (int j = 0; j < TN; j++) {
            int n = n0 + tx * TN + j;
            float v = acc[i][j];
            if (MODE == 2) v = fmaxf(v + bias[n], 0.f);
            C[(size_t)m * ldc + n] = v;
        }
    }
}

__global__ void head2_kernel(const float* __restrict__ hid,
                             const float* __restrict__ W2,
                             const float* __restrict__ b2,
                             float* __restrict__ out)
{
    __shared__ float red[256];
    int b = blockIdx.x;
    float s = 0.f;
    for (int i = threadIdx.x; i < 2 * H_SZ; i += 256)
        s += hid[(size_t)b * 2 * H_SZ + i] * W2[i];
    red[threadIdx.x] = s;
    __syncthreads();
    for (int off = 128; off > 0; off >>= 1) {
        if (threadIdx.x < off) red[threadIdx.x] += red[threadIdx.x + off];
        __syncthreads();
    }
    if (threadIdx.x == 0) out[b] = red[0] + b2[0];
}

// ---------------- host ----------------
extern "C" void kernel_launch(void* const* d_in, const int* in_sizes, int n_in,
                              void* d_out, int out_size)
{
    const int*   x       = (const int*)  d_in[0];
    const float* embed_W = (const float*)d_in[1];
    const float* W_ih    = (const float*)d_in[2];
    const float* b_ih    = (const float*)d_in[3];
    const float* W1      = (const float*)d_in[4];
    const float* b1      = (const float*)d_in[5];
    const float* W2      = (const float*)d_in[6];
    const float* b2      = (const float*)d_in[7];
    float*       out     = (float*)d_out;

    float *hlast, *hid;
    int *cnt, *bar;
    __nv_bfloat16 *hhi0, *hlo0, *whi, *wlo;
    cudaGetSymbolAddress((void**)&hlast, g_hlast);
    cudaGetSymbolAddress((void**)&hid,   g_hid);
    cudaGetSymbolAddress((void**)&cnt,   g_cnt);
    cudaGetSymbolAddress((void**)&bar,   g_bar);
    {
        __nv_bfloat16* p;
        cudaGetSymbolAddress((void**)&p, g_h_hi); hhi0 = p;
        cudaGetSymbolAddress((void**)&p, g_h_lo); hlo0 = p;
        cudaGetSymbolAddress((void**)&p, g_w_hi); whi = p;
        cudaGetSymbolAddress((void**)&p, g_w_lo); wlo = p;
    }

    static bool attr_done = false;
    if (!attr_done) {
        cudaFuncSetAttribute(rnn_kernel,
            cudaFuncAttributeMaxDynamicSharedMemorySize, SMEM_RNN);
        cudaFuncSetAttribute(table_mma_kernel,
            cudaFuncAttributeMaxDynamicSharedMemorySize, SMEM_TAB);
        attr_done = true;
    }

    // init, splits
    init_kernel<<<(B_SZ * H_SZ) / 256, 256>>>(hhi0, hlo0, cnt, bar);
    split_w_kernel<<<(H_SZ * H_SZ) / 256, 256>>>(W_ih, whi, wlo);
    split_e_kernel<<<(int)(((size_t)V_SZ * KP) / 256), 256>>>(embed_W);
    split_we_kernel<<<(H_SZ * KP) / 256, 256>>>(W_ih);

    // vocab table on tensor cores
    table_mma_kernel<<<dim3(H_SZ / 64, (V_SZ + 127) / 128), 256, SMEM_TAB>>>();

    // all 512 recurrence steps in ONE persistent kernel
    rnn_kernel<<<NCTA, 512, SMEM_RNN>>>(x, b_ih);

    // h_last = dbuf[0] after 512 steps
    recon_h_kernel<<<(B_SZ * H_SZ) / 256, 256>>>(hhi0, hlo0, hlast);

    gemm_nt<64, 64, 32, 4, 4, 2, false>
        <<<dim3(2 * H_SZ / 64, B_SZ / 64), 256>>>(
            hlast, H_SZ, W1, H_SZ, hid, 2 * H_SZ,
            B_SZ, 2 * H_SZ, H_SZ, b1);

    head2_kernel<<<B_SZ, 256>>>(hid, W2, b2, out);
}

// round 7
// speedup vs baseline: 3.9589x; 1.0282x over previous
#include <cuda_runtime.h>
#include <cuda_bf16.h>
#include <math.h>
#include <stdint.h>

#define B_SZ 256
#define S_SZ 512
#define V_SZ 50000
#define E_SZ 300
#define H_SZ 1024
#define KP   320

// persistent tiling: 4 mtiles(64) x 8 ntiles(128) x 4 kq(256) = 128 CTAs
#define NCTA     128
#define MT       64
#define NTN      128
#define KQ       256
#define SW_BYTES   131072          // W: [2 term][8 ch][128 r][64B]
#define SH_BYTES   65536           // h: [2 buf][2 term][4 sub][64 r][64B]
#define SMEM_RNN   (SW_BYTES + SH_BYTES)

#define TB_STG   24576
#define SMEM_TAB (3 * TB_STG)

// ---------------- scratch ----------------
__device__ __align__(128) __nv_bfloat16 g_h_hi[2][B_SZ * H_SZ];
__device__ __align__(128) __nv_bfloat16 g_h_lo[2][B_SZ * H_SZ];
__device__ __align__(128) __nv_bfloat16 g_w_hi[H_SZ * H_SZ];
__device__ __align__(128) __nv_bfloat16 g_w_lo[H_SZ * H_SZ];
__device__ __align__(128) __nv_bfloat16 g_e_hi[(size_t)V_SZ * KP];
__device__ __align__(128) __nv_bfloat16 g_e_lo[(size_t)V_SZ * KP];
__device__ __align__(128) __nv_bfloat16 g_we_hi[H_SZ * KP];
__device__ __align__(128) __nv_bfloat16 g_we_lo[H_SZ * KP];
__device__ float g_table[(size_t)V_SZ * H_SZ];
__device__ float g_hlast[B_SZ * H_SZ];
__device__ float g_hid[B_SZ * 2 * H_SZ];
__device__ __align__(128) float g_part[32 * 4 * MT * NTN];
__device__ int g_cnt[32];
__device__ int g_done[32];

// ---------------- PTX helpers ----------------
__device__ __forceinline__ uint32_t smem_u32(const void* p) {
    return (uint32_t)__cvta_generic_to_shared(p);
}
__device__ __forceinline__ void cp16(uint32_t dst, const void* src) {
    asm volatile("cp.async.cg.shared.global [%0], [%1], 16;" :: "r"(dst), "l"(src));
}
#define CP_COMMIT() asm volatile("cp.async.commit_group;" ::: "memory")
#define CP_WAIT_G2() asm volatile("cp.async.wait_group 2;" ::: "memory")
#define CP_WAIT_G1() asm volatile("cp.async.wait_group 1;" ::: "memory")
#define CP_WAIT_G0() asm volatile("cp.async.wait_group 0;" ::: "memory")
__device__ __forceinline__ void l2pf(const void* p) {
    asm volatile("prefetch.global.L2 [%0];" :: "l"(p));
}
__device__ __forceinline__ void ldmx4(uint32_t* r, uint32_t addr) {
    asm volatile("ldmatrix.sync.aligned.m8n8.x4.shared.b16 {%0,%1,%2,%3}, [%4];"
        : "=r"(r[0]), "=r"(r[1]), "=r"(r[2]), "=r"(r[3]) : "r"(addr));
}
__device__ __forceinline__ void mma16816(float* d, const uint32_t* a,
                                         const uint32_t b0, const uint32_t b1) {
    asm volatile("mma.sync.aligned.m16n8k16.row.col.f32.bf16.bf16.f32 "
        "{%0,%1,%2,%3}, {%4,%5,%6,%7}, {%8,%9}, {%0,%1,%2,%3};"
        : "+f"(d[0]), "+f"(d[1]), "+f"(d[2]), "+f"(d[3])
        : "r"(a[0]), "r"(a[1]), "r"(a[2]), "r"(a[3]), "r"(b0), "r"(b1));
}

// ---------------- persistent RNN kernel (512 threads) ----------------
__global__ void __launch_bounds__(512, 1) rnn_kernel(
    const int* __restrict__ x,
    const float* __restrict__ bias)
{
    extern __shared__ __align__(128) char smem[];
    const uint32_t sw = smem_u32(smem);
    const uint32_t sh = sw + SW_BYTES;

    const int tid  = threadIdx.x;
    const int lane = tid & 31;
    const int wid  = tid >> 5;
    const int wm   = wid >> 2;          // 0..3
    const int wn   = wid & 3;           // 0..3
    const int cta  = blockIdx.x;
    const int kq   = cta & 3;
    const int nidx = (cta >> 2) & 7;
    const int midx = cta >> 5;
    const int m0g  = midx * MT;
    const int n0g  = nidx * NTN;
    const int kbase = kq * KQ;
    const int tile  = midx * 8 + nidx;
    const int feedA = midx * 8 + 2 * kq;
    const int feedB = feedA + 1;

    // ---- W slice into smem (once) ----
    {
#pragma unroll
        for (int i = 0; i < 16; i++) {
            int u = tid + i * 512;
            int term = u >> 12;
            int v = u & 4095;
            int ch = v >> 9;
            int w2 = v & 511;
            int r = w2 >> 2, c = w2 & 3;
            const __nv_bfloat16* src = (term ? g_w_lo : g_w_hi)
                + (size_t)(n0g + r) * H_SZ + kbase + ch * 32 + c * 8;
            uint32_t dst = sw + term * 65536 + ch * 8192 + r * 64
                         + ((c ^ ((r >> 1) & 3)) << 4);
            cp16(dst, src);
        }
        CP_COMMIT(); CP_WAIT_G0();
        __syncthreads();
    }

    // ldmatrix lane geometry (warp tile 16M x 32N)
    const int rA = wm * 16 + (lane & 15);
    const int cAadd = lane >> 4;
    const int swzA = (rA >> 1) & 3;
    const int rowB0 = wn * 32 + ((lane >> 4) << 3) + (lane & 7);
    const int rowB1 = rowB0 + 16;
    const int cBadd = (lane >> 3) & 1;
    const int swzB = (rowB0 >> 1) & 3;

    // issue one 32KB h half (128 K-cols): 2048 units, 4/thread
    auto issue_half = [&](const __nv_bfloat16* hhi_in,
                          const __nv_bfloat16* hlo_in, int buf) {
#pragma unroll
        for (int i = 0; i < 4; i++) {
            int v = tid + i * 512;
            int term = v >> 10;
            int w = v & 1023;
            int sub = w >> 8;
            int z = w & 255;
            int r = z >> 2, c = z & 3;
            const __nv_bfloat16* src = (term ? hlo_in : hhi_in)
                + (size_t)(m0g + r) * H_SZ + kbase + buf * 128 + sub * 32 + c * 8;
            uint32_t dst = sh + buf * 32768 + term * 16384 + sub * 4096
                         + r * 64 + ((c ^ ((r >> 1) & 3)) << 4);
            cp16(dst, src);
        }
        CP_COMMIT();
    };

    float acc[4][4];

    auto compute_half = [&](int buf) {
        const uint32_t hb = sh + buf * 32768;
#pragma unroll
        for (int kk2 = 0; kk2 < 8; kk2++) {
            const int sub = kk2 >> 1, kkin = kk2 & 1;
            const uint32_t hst = hb + sub * 4096;
            const uint32_t wst = sw + (buf * 4 + sub) * 8192;
            const int cA = ((kkin * 2 + cAadd) ^ swzA) << 4;
            const int cB = ((kkin * 2 + cBadd) ^ swzB) << 4;
            uint32_t ahi[4], alo[4], bhi[8], blo[8];
            ldmx4(ahi, hst + rA * 64 + cA);
            ldmx4(alo, hst + 16384 + rA * 64 + cA);
            ldmx4(bhi,     wst + rowB0 * 64 + cB);
            ldmx4(bhi + 4, wst + rowB1 * 64 + cB);
            ldmx4(blo,     wst + 65536 + rowB0 * 64 + cB);
            ldmx4(blo + 4, wst + 65536 + rowB1 * 64 + cB);
#pragma unroll
            for (int j = 0; j < 4; j++) {
                const uint32_t* b = &bhi[(j >> 1) * 4 + (j & 1) * 2];
                mma16816(acc[j], ahi, b[0], b[1]);
            }
#pragma unroll
            for (int j = 0; j < 4; j++) {
                const uint32_t* b = &blo[(j >> 1) * 4 + (j & 1) * 2];
                mma16816(acc[j], ahi, b[0], b[1]);
            }
#pragma unroll
            for (int j = 0; j < 4; j++) {
                const uint32_t* b = &bhi[(j >> 1) * 4 + (j & 1) * 2];
                mma16816(acc[j], alo, b[0], b[1]);
            }
        }
    };

    for (int t = 0; t < S_SZ; t++) {
        const __nv_bfloat16* hhi_in = g_h_hi[t & 1];
        const __nv_bfloat16* hlo_in = g_h_lo[t & 1];
        __nv_bfloat16* hhi_out = g_h_hi[(t + 1) & 1];
        __nv_bfloat16* hlo_out = g_h_lo[(t + 1) & 1];

        // ---- point-to-point readiness: h(t) from feeds, partial WAR on mytile
        if (t > 0 && tid == 0) {
            const int tgt = 4 * t;
            while (*(volatile int*)&g_done[feedA] < tgt) __nanosleep(32);
            while (*(volatile int*)&g_done[feedB] < tgt) __nanosleep(32);
            while (*(volatile int*)&g_done[tile]  < tgt) __nanosleep(32);
            __threadfence();
        }
        __syncthreads();

        // table L2 prefetch for my 16-row quarter
        if (tid < 16) {
            int gr = m0g + kq * 16 + tid;
            int tok = x[(size_t)gr * S_SZ + t];
            const char* p = (const char*)(g_table + (size_t)tok * H_SZ + n0g);
            l2pf(p); l2pf(p + 128); l2pf(p + 256); l2pf(p + 384);
        }

        issue_half(hhi_in, hlo_in, 0);
        issue_half(hhi_in, hlo_in, 1);

#pragma unroll
        for (int j = 0; j < 4; j++)
#pragma unroll
            for (int q = 0; q < 4; q++) acc[j][q] = 0.f;

        CP_WAIT_G1();
        __syncthreads();
        compute_half(0);
        CP_WAIT_G0();
        __syncthreads();
        compute_half(1);

        // ---- write my partial ----
        {
            float* pb = g_part + ((size_t)tile * 4 + kq) * (MT * NTN);
            const int r = wm * 16 + (lane >> 2);
#pragma unroll
            for (int j = 0; j < 4; j++) {
                const int c = wn * 32 + j * 8 + 2 * (lane & 3);
                *reinterpret_cast<float2*>(pb + r * NTN + c) =
                    make_float2(acc[j][0], acc[j][1]);
                *reinterpret_cast<float2*>(pb + (r + 8) * NTN + c) =
                    make_float2(acc[j][2], acc[j][3]);
            }
        }
        __threadfence();
        __syncthreads();
        if (tid == 0) {
            atomicAdd(&g_cnt[tile], 1);
            const int tgt = 4 * (t + 1);
            while (*(volatile int*)&g_cnt[tile] < tgt) __nanosleep(32);
            __threadfence();
        }
        __syncthreads();

        // ---- reduce my 16-row quarter + epilogue ----
        {
            const int rloc = tid >> 5;
            const int c0   = lane * 4;
            const int pr   = kq * 16 + rloc;
            const int gr   = m0g + pr;
            const float* pb = g_part + (size_t)tile * 4 * (MT * NTN)
                            + pr * NTN + c0;
            float4 s = make_float4(0.f, 0.f, 0.f, 0.f);
#pragma unroll
            for (int q = 0; q < 4; q++) {
                float4 a = *reinterpret_cast<const float4*>(pb + q * (MT * NTN));
                s.x += a.x; s.y += a.y; s.z += a.z; s.w += a.w;
            }
            const int tok = x[(size_t)gr * S_SZ + t];
            float4 tv = *reinterpret_cast<const float4*>(
                g_table + (size_t)tok * H_SZ + n0g + c0);
            float4 bv = *reinterpret_cast<const float4*>(bias + n0g + c0);
            float v0 = tanhf(s.x + tv.x + bv.x);
            float v1 = tanhf(s.y + tv.y + bv.y);
            float v2 = tanhf(s.z + tv.z + bv.z);
            float v3 = tanhf(s.w + tv.w + bv.w);
            __nv_bfloat16 h4[4], l4[4];
            h4[0] = __float2bfloat16(v0); l4[0] = __float2bfloat16(v0 - __bfloat162float(h4[0]));
            h4[1] = __float2bfloat16(v1); l4[1] = __float2bfloat16(v1 - __bfloat162float(h4[1]));
            h4[2] = __float2bfloat16(v2); l4[2] = __float2bfloat16(v2 - __bfloat162float(h4[2]));
            h4[3] = __float2bfloat16(v3); l4[3] = __float2bfloat16(v3 - __bfloat162float(h4[3]));
            const size_t ob = (size_t)gr * H_SZ + n0g + c0;
            *reinterpret_cast<uint2*>(hhi_out + ob) = *reinterpret_cast<uint2*>(h4);
            *reinterpret_cast<uint2*>(hlo_out + ob) = *reinterpret_cast<uint2*>(l4);
        }
        __threadfence();
        __syncthreads();
        if (tid == 0) atomicAdd(&g_done[tile], 1);
    }
}

// ---------------- table GEMM on tensor cores ----------------
__global__ void __launch_bounds__(256) table_mma_kernel()
{
    extern __shared__ __align__(128) char smem[];
    const uint32_t sb = smem_u32(smem);
    const int tid  = threadIdx.x;
    const int lane = tid & 31;
    const int wid  = tid >> 5;
    const int wm   = wid >> 1;
    const int wn   = wid & 1;
    const int n0   = blockIdx.x * 64;
    const int m0   = blockIdx.y * 128;

    auto issue_tab = [&](uint32_t sbase, int ch) {
#pragma unroll
        for (int i = 0; i < 6; i++) {
            int u = tid + i * 256;
            if (u < 1024) {
                int term = u >> 9;
                int v = u & 511;
                int r = v >> 2, c = v & 3;
                int gm = m0 + r; if (gm >= V_SZ) gm = V_SZ - 1;
                const __nv_bfloat16* src = (term ? g_e_lo : g_e_hi)
                    + (size_t)gm * KP + ch * 32 + c * 8;
                uint32_t dst = sbase + term * 8192 + r * 64
                             + ((c ^ ((r >> 1) & 3)) << 4);
                cp16(dst, src);
            } else {
                int v = u - 1024;
                int term = v >> 8;
                v &= 255;
                int r = v >> 2, c = v & 3;
                const __nv_bfloat16* src = (term ? g_we_lo : g_we_hi)
                    + (size_t)(n0 + r) * KP + ch * 32 + c * 8;
                uint32_t dst = sbase + 16384 + term * 4096 + r * 64
                             + ((c ^ ((r >> 1) & 3)) << 4);
                cp16(dst, src);
            }
        }
        CP_COMMIT();
    };

    issue_tab(sb + 0 * TB_STG, 0);
    issue_tab(sb + 1 * TB_STG, 1);
    issue_tab(sb + 2 * TB_STG, 2);

    const int rA0 = wm * 32 + (lane & 15);
    const int rA1 = rA0 + 16;
    const int cAadd = lane >> 4;
    const int swzA = (rA0 >> 1) & 3;
    const int rowB0 = wn * 32 + ((lane >> 4) << 3) + (lane & 7);
    const int rowB1 = rowB0 + 16;
    const int cBadd = (lane >> 3) & 1;
    const int swzB = (rowB0 >> 1) & 3;

    float acc[2][4][4];
#pragma unroll
    for (int i = 0; i < 2; i++)
#pragma unroll
        for (int j = 0; j < 4; j++)
#pragma unroll
            for (int q = 0; q < 4; q++) acc[i][j][q] = 0.f;

    const int NCH = KP / 32;
    for (int ch = 0; ch < NCH; ch++) {
        CP_WAIT_G2();
        __syncthreads();
        const uint32_t st = sb + (ch % 3) * TB_STG;
#pragma unroll
        for (int kk = 0; kk < 2; kk++) {
            const int cA = ((kk * 2 + cAadd) ^ swzA) << 4;
            const int cB = ((kk * 2 + cBadd) ^ swzB) << 4;
            uint32_t ahi[8], alo[8], bhi[8], blo[8];
            ldmx4(ahi,     st + rA0 * 64 + cA);
            ldmx4(ahi + 4, st + rA1 * 64 + cA);
            ldmx4(alo,     st + 8192 + rA0 * 64 + cA);
            ldmx4(alo + 4, st + 8192 + rA1 * 64 + cA);
            ldmx4(bhi,     st + 16384 + rowB0 * 64 + cB);
            ldmx4(bhi + 4, st + 16384 + rowB1 * 64 + cB);
            ldmx4(blo,     st + 20480 + rowB0 * 64 + cB);
            ldmx4(blo + 4, st + 20480 + rowB1 * 64 + cB);
#pragma unroll
            for (int i = 0; i < 2; i++)
#pragma unroll
                for (int j = 0; j < 4; j++) {
                    const uint32_t* b = &bhi[(j >> 1) * 4 + (j & 1) * 2];
                    mma16816(acc[i][j], ahi + i * 4, b[0], b[1]);
                }
#pragma unroll
            for (int i = 0; i < 2; i++)
#pragma unroll
                for (int j = 0; j < 4; j++) {
                    const uint32_t* b = &blo[(j >> 1) * 4 + (j & 1) * 2];
                    mma16816(acc[i][j], ahi + i * 4, b[0], b[1]);
                }
#pragma unroll
            for (int i = 0; i < 2; i++)
#pragma unroll
                for (int j = 0; j < 4; j++) {
                    const uint32_t* b = &bhi[(j >> 1) * 4 + (j & 1) * 2];
                    mma16816(acc[i][j], alo + i * 4, b[0], b[1]);
                }
        }
        __syncthreads();
        if (ch + 3 < NCH) issue_tab(sb + (ch % 3) * TB_STG, ch + 3);
        else CP_COMMIT();
    }

#pragma unroll
    for (int i = 0; i < 2; i++) {
        const int r = wm * 32 + i * 16 + (lane >> 2);
#pragma unroll
        for (int j = 0; j < 4; j++) {
            const int c = wn * 32 + j * 8 + 2 * (lane & 3);
            int gm = m0 + r;
            if (gm < V_SZ)
                *reinterpret_cast<float2*>(g_table + (size_t)gm * H_SZ + n0 + c) =
                    make_float2(acc[i][j][0], acc[i][j][1]);
            if (gm + 8 < V_SZ)
                *reinterpret_cast<float2*>(g_table + (size_t)(gm + 8) * H_SZ + n0 + c) =
                    make_float2(acc[i][j][2], acc[i][j][3]);
        }
    }
}

// ---------------- prep / misc ----------------
__global__ void split_w_kernel(const float* __restrict__ W_ih,
                               __nv_bfloat16* __restrict__ whi,
                               __nv_bfloat16* __restrict__ wlo)
{
    int i = blockIdx.x * 256 + threadIdx.x;
    int j = i >> 10, k = i & (H_SZ - 1);
    float w = W_ih[(size_t)j * (E_SZ + H_SZ) + E_SZ + k];
    __nv_bfloat16 hi = __float2bfloat16(w);
    whi[i] = hi;
    wlo[i] = __float2bfloat16(w - __bfloat162float(hi));
}

__global__ void split_e_kernel(const float* __restrict__ embed_W)
{
    size_t id = (size_t)blockIdx.x * 256 + threadIdx.x;
    int row = (int)(id / KP);
    int col = (int)(id - (size_t)row * KP);
    float v = (col < E_SZ) ? embed_W[(size_t)row * E_SZ + col] : 0.f;
    __nv_bfloat16 hi = __float2bfloat16(v);
    g_e_hi[id] = hi;
    g_e_lo[id] = __float2bfloat16(v - __bfloat162float(hi));
}

__global__ void split_we_kernel(const float* __restrict__ W_ih)
{
    int id = blockIdx.x * 256 + threadIdx.x;
    int row = id / KP;
    int col = id - row * KP;
    float v = (col < E_SZ) ? W_ih[(size_t)row * (E_SZ + H_SZ) + col] : 0.f;
    __nv_bfloat16 hi = __float2bfloat16(v);
    g_we_hi[id] = hi;
    g_we_lo[id] = __float2bfloat16(v - __bfloat162float(hi));
}

__global__ void init_kernel(__nv_bfloat16* hi, __nv_bfloat16* lo,
                            int* cnt, int* done) {
    int i = blockIdx.x * 256 + threadIdx.x;
    hi[i] = __float2bfloat16(0.f);
    lo[i] = __float2bfloat16(0.f);
    if (i < 32) { cnt[i] = 0; done[i] = 0; }
}

__global__ void recon_h_kernel(const __nv_bfloat16* __restrict__ hi,
                               const __nv_bfloat16* __restrict__ lo,
                               float* __restrict__ out) {
    int i = blockIdx.x * 256 + threadIdx.x;
    out[i] = __bfloat162float(hi[i]) + __bfloat162float(lo[i]);
}

// ---------------- SIMT GEMM (MLP L1 only) ----------------
template<int BM, int BN, int BK, int TM, int TN, int MODE>
__global__ void __launch_bounds__(256) gemm_nt(
    const float* __restrict__ A, int lda,
    const float* __restrict__ B, int ldb,
    float* __restrict__ C, int ldc,
    int M, int N, int K,
    const float* __restrict__ bias)
{
    constexpr int BNP = BN + 1;
    __shared__ float As[BM * BK];
    __shared__ float Bs[BK * BNP];
    const int tid = threadIdx.x;
    const int tx = tid % (BN / TN);
    const int ty = tid / (BN / TN);
    const int m0 = blockIdx.y * BM;
    const int n0 = blockIdx.x * BN;
    constexpr int A_LD = (BM * BK / 4) / 256;
    constexpr int B_LD = (BN * BK / 4) / 256;
    float4 aReg[A_LD], bReg[B_LD];
    const int KT = (K + BK - 1) / BK;

    auto loadA = [&](int kt) {
#pragma unroll
        for (int i = 0; i < A_LD; i++) {
            int idx = tid + i * 256;
            int r = idx / (BK / 4), c4 = idx % (BK / 4);
            int gm = m0 + r, gk = kt * BK + c4 * 4;
            aReg[i] = *reinterpret_cast<const float4*>(&A[(size_t)gm * lda + gk]);
        }
    };
    auto loadB = [&](int kt) {
#pragma unroll
        for (int i = 0; i < B_LD; i++) {
            int idx = tid + i * 256;
            int r = idx / (BK / 4), c4 = idx % (BK / 4);
            int gn = n0 + r, gk = kt * BK + c4 * 4;
            bReg[i] = *reinterpret_cast<const float4*>(&B[(size_t)gn * ldb + gk]);
        }
    };
    auto storeA = [&]() {
#pragma unroll
        for (int i = 0; i < A_LD; i++) {
            int idx = tid + i * 256;
            int r = idx / (BK / 4), c4 = idx % (BK / 4);
            *reinterpret_cast<float4*>(&As[r * BK + c4 * 4]) = aReg[i];
        }
    };
    auto storeB = [&]() {
#pragma unroll
        for (int i = 0; i < B_LD; i++) {
            int idx = tid + i * 256;
            int r = idx / (BK / 4), c4 = idx % (BK / 4);
            int kb = c4 * 4;
            float4 v = bReg[i];
            Bs[(kb + 0) * BNP + r] = v.x;
            Bs[(kb + 1) * BNP + r] = v.y;
            Bs[(kb + 2) * BNP + r] = v.z;
            Bs[(kb + 3) * BNP + r] = v.w;
        }
    };

    float acc[TM][TN];
#pragma unroll
    for (int i = 0; i < TM; i++)
#pragma unroll
        for (int j = 0; j < TN; j++) acc[i][j] = 0.f;

    loadA(0); loadB(0); storeA(); storeB();
    __syncthreads();
    for (int kt = 0; kt < KT; kt++) {
        if (kt + 1 < KT) { loadA(kt + 1); loadB(kt + 1); }
#pragma unroll
        for (int kk = 0; kk < BK; kk++) {
            float a[TM], b[TN];
#pragma unroll
            for (int i = 0; i < TM; i++) a[i] = As[(ty * TM + i) * BK + kk];
#pragma unroll
            for (int j = 0; j < TN; j++) b[j] = Bs[kk * BNP + tx * TN + j];
#pragma unroll
            for (int i = 0; i < TM; i++)
#pragma unroll
                for (int j = 0; j < TN; j++)
                    acc[i][j] = fmaf(a[i], b[j], acc[i][j]);
        }
        __syncthreads();
        if (kt + 1 < KT) { storeA(); storeB(); }
        __syncthreads();
    }
#pragma unroll
    for (int i = 0; i < TM; i++) {
        int m = m0 + ty * TM + i;
#pragma unroll
        for (int j = 0; j < TN; j++) {
            int n = n0 + tx * TN + j;
            float v = acc[i][j];
            if (MODE == 2) v = fmaxf(v + bias[n], 0.f);
            C[(size_t)m * ldc + n] = v;
        }
    }
}

__global__ void head2_kernel(const float* __restrict__ hid,
                             const float* __restrict__ W2,
                             const float* __restrict__ b2,
                             float* __restrict__ out)
{
    __shared__ float red[256];
    int b = blockIdx.x;
    float s = 0.f;
    for (int i = threadIdx.x; i < 2 * H_SZ; i += 256)
        s += hid[(size_t)b * 2 * H_SZ + i] * W2[i];
    red[threadIdx.x] = s;
    __syncthreads();
    for (int off = 128; off > 0; off >>= 1) {
        if (threadIdx.x < off) red[threadIdx.x] += red[threadIdx.x + off];
        __syncthreads();
    }
    if (threadIdx.x == 0) out[b] = red[0] + b2[0];
}

// ---------------- host ----------------
extern "C" void kernel_launch(void* const* d_in, const int* in_sizes, int n_in,
                              void* d_out, int out_size)
{
    const int*   x       = (const int*)  d_in[0];
    const float* embed_W = (const float*)d_in[1];
    const float* W_ih    = (const float*)d_in[2];
    const float* b_ih    = (const float*)d_in[3];
    const float* W1      = (const float*)d_in[4];
    const float* b1      = (const float*)d_in[5];
    const float* W2      = (const float*)d_in[6];
    const float* b2      = (const float*)d_in[7];
    float*       out     = (float*)d_out;

    float *hlast, *hid;
    int *cnt, *done;
    __nv_bfloat16 *hhi0, *hlo0, *whi, *wlo;
    cudaGetSymbolAddress((void**)&hlast, g_hlast);
    cudaGetSymbolAddress((void**)&hid,   g_hid);
    cudaGetSymbolAddress((void**)&cnt,   g_cnt);
    cudaGetSymbolAddress((void**)&done,  g_done);
    {
        __nv_bfloat16* p;
        cudaGetSymbolAddress((void**)&p, g_h_hi); hhi0 = p;
        cudaGetSymbolAddress((void**)&p, g_h_lo); hlo0 = p;
        cudaGetSymbolAddress((void**)&p, g_w_hi); whi = p;
        cudaGetSymbolAddress((void**)&p, g_w_lo); wlo = p;
    }

    static bool attr_done = false;
    if (!attr_done) {
        cudaFuncSetAttribute(rnn_kernel,
            cudaFuncAttributeMaxDynamicSharedMemorySize, SMEM_RNN);
        cudaFuncSetAttribute(table_mma_kernel,
            cudaFuncAttributeMaxDynamicSharedMemorySize, SMEM_TAB);
        attr_done = true;
    }

    init_kernel<<<(B_SZ * H_SZ) / 256, 256>>>(hhi0, hlo0, cnt, done);
    split_w_kernel<<<(H_SZ * H_SZ) / 256, 256>>>(W_ih, whi, wlo);
    split_e_kernel<<<(int)(((size_t)V_SZ * KP) / 256), 256>>>(embed_W);
    split_we_kernel<<<(H_SZ * KP) / 256, 256>>>(W_ih);

    table_mma_kernel<<<dim3(H_SZ / 64, (V_SZ + 127) / 128), 256, SMEM_TAB>>>();

    rnn_kernel<<<NCTA, 512, SMEM_RNN>>>(x, b_ih);

    recon_h_kernel<<<(B_SZ * H_SZ) / 256, 256>>>(hhi0, hlo0, hlast);

    gemm_nt<64, 64, 32, 4, 4, 2>
        <<<dim3(2 * H_SZ / 64, B_SZ / 64), 256>>>(
            hlast, H_SZ, W1, H_SZ, hid, 2 * H_SZ,
            B_SZ, 2 * H_SZ, H_SZ, b1);

    head2_kernel<<<B_SZ, 256>>>(hid, W2, b2, out);
}